// round 3
// baseline (speedup 1.0000x reference)
#include <cuda_runtime.h>
#include <math.h>

#define NB 64
#define NPIX 596
#define HEADS 4
#define DH 64
#define PER_B (HEADS*NPIX*DH)   // 152576

#define TI2 60                  // rows per attention block (10 tiles -> 600 rows)
#define NRP (TI2/2)             // 30 row-pairs
#define ATHR 320
#define APAD 68                 // stride: 16B-aligned rows, 4-way softmax conflicts only
#define SMEM_FLOATS (NPIX*APAD + 2*DH*APAD)   // 40528 + 8704 = 49232
#define SMEM_BYTES (SMEM_FLOATS*4)            // 196928

// ---------------- scratch (device globals, no allocation) ----------------
__device__ float g_conv1[NB*16*150*5];
__device__ float g_feats[NB*NPIX*34];
__device__ float g_K[NB*HEADS*NPIX*DH];
__device__ float g_Q[NB*HEADS*NPIX*DH];
__device__ float g_V[NB*HEADS*NPIX*DH];
__device__ float g_mu[3*NB], g_rv[3*NB];
__device__ float g_E[NB*NPIX*256];
__device__ float g_F[NB*NPIX*DH];
__device__ float g_mu2[NB], g_rv2[NB];
__device__ float g_M[NB*DH];

__device__ __forceinline__ float eluf(float x) {
    return x > 0.f ? x : (__expf(x) - 1.f);
}

// packed fp32x2 helpers (sm_103a)
__device__ __forceinline__ void ffma2(unsigned long long &acc,
                                      unsigned long long a,
                                      unsigned long long b) {
    asm("fma.rn.f32x2 %0, %1, %2, %0;" : "+l"(acc) : "l"(a), "l"(b));
}
__device__ __forceinline__ unsigned long long dup2(float x) {
    unsigned long long r;
    asm("mov.b64 %0, {%1, %1};" : "=l"(r) : "f"(x));
    return r;
}
__device__ __forceinline__ float lo2(unsigned long long v) {
    float a, b;
    asm("mov.b64 {%0, %1}, %2;" : "=f"(a), "=f"(b) : "l"(v));
    return a;
}
__device__ __forceinline__ float hi2(unsigned long long v) {
    float a, b;
    asm("mov.b64 {%0, %1}, %2;" : "=f"(a), "=f"(b) : "l"(v));
    return b;
}

// ---------------- conv1 + relu ----------------
__global__ void conv1_kernel(const float* __restrict__ x,
                             const float* __restrict__ w,
                             const float* __restrict__ b) {
    int idx = blockIdx.x * blockDim.x + threadIdx.x;
    if (idx >= NB*16*150*5) return;
    int ow = idx % 5;
    int oh = (idx / 5) % 150;
    int co = (idx / (5*150)) % 16;
    int bb = idx / (5*150*16);
    float acc = b[co];
    #pragma unroll
    for (int ci = 0; ci < 4; ci++)
        #pragma unroll
        for (int kh = 0; kh < 2; kh++)
            #pragma unroll
            for (int kw = 0; kw < 2; kw++)
                acc += x[((bb*4+ci)*151 + oh+kh)*6 + ow+kw] *
                       w[((co*4+ci)*2 + kh)*2 + kw];
    g_conv1[idx] = fmaxf(acc, 0.f);
}

// ---------------- conv2 + relu + coords -> feats (N, 596, 34) ----------------
__global__ void conv2_feats_kernel(const float* __restrict__ w,
                                   const float* __restrict__ b) {
    int idx = blockIdx.x * blockDim.x + threadIdx.x;
    if (idx >= NB*NPIX*34) return;
    int c = idx % 34;
    int p = (idx / 34) % NPIX;
    int bb = idx / (34*NPIX);
    int oh = p / 4, ow = p % 4;
    float val;
    if (c < 32) {
        float acc = b[c];
        #pragma unroll 4
        for (int ci = 0; ci < 16; ci++)
            #pragma unroll
            for (int kh = 0; kh < 2; kh++)
                #pragma unroll
                for (int kw = 0; kw < 2; kw++)
                    acc += g_conv1[((bb*16+ci)*150 + oh+kh)*5 + ow+kw] *
                           w[((c*16+ci)*2 + kh)*2 + kw];
        val = fmaxf(acc, 0.f);
    } else if (c == 32) {
        val = (float)ow / 4.f;
    } else {
        val = (float)oh / 149.f;
    }
    g_feats[idx] = val;
}

// ---------------- K/Q/V projections (b,p,hd) -> [b][h][p][d] ----------------
__global__ void proj_kernel(const float* __restrict__ kw, const float* __restrict__ kb,
                            const float* __restrict__ qw, const float* __restrict__ qb,
                            const float* __restrict__ vw, const float* __restrict__ vb) {
    int t = blockIdx.y;
    const float* W = t==0 ? kw : t==1 ? qw : vw;
    const float* B = t==0 ? kb : t==1 ? qb : vb;
    float* O = t==0 ? g_K : t==1 ? g_Q : g_V;
    int idx = blockIdx.x * blockDim.x + threadIdx.x;
    if (idx >= NB*NPIX*256) return;
    int hd = idx & 255;
    int bp = idx >> 8;
    int p = bp % NPIX, bb = bp / NPIX;
    const float* f = g_feats + bp*34;
    float acc = B[hd];
    #pragma unroll
    for (int c = 0; c < 34; c++) acc += f[c] * W[c*256 + hd];
    int h = hd >> 6, d = hd & 63;
    O[((bb*HEADS + h)*NPIX + p)*DH + d] = acc;
}

// ---------------- LN stats over (h,p,d) per batch (float accum) ----------------
__global__ void ln_stats_kernel() {
    int bb = blockIdx.x, t = blockIdx.y;
    const float* base = (t==0 ? g_K : t==1 ? g_Q : g_V) + bb*PER_B;
    float s = 0.f, ss = 0.f;
    for (int i = threadIdx.x; i < PER_B; i += blockDim.x) {
        float v = base[i]; s += v; ss += v*v;
    }
    __shared__ double sh[256], sh2[256];
    sh[threadIdx.x] = (double)s; sh2[threadIdx.x] = (double)ss; __syncthreads();
    for (int o = 128; o; o >>= 1) {
        if (threadIdx.x < o) { sh[threadIdx.x] += sh[threadIdx.x+o]; sh2[threadIdx.x] += sh2[threadIdx.x+o]; }
        __syncthreads();
    }
    if (threadIdx.x == 0) {
        double m = sh[0] / (double)PER_B;
        double var = sh2[0] / (double)PER_B - m*m;
        g_mu[t*NB+bb] = (float)m;
        g_rv[t*NB+bb] = (float)(1.0 / sqrt(var + 1e-5));
    }
}

// ---------------- LN apply (with affine g,b) in place ----------------
__global__ void ln_apply_kernel(const float* __restrict__ kg, const float* __restrict__ kb,
                                const float* __restrict__ qg, const float* __restrict__ qb,
                                const float* __restrict__ vg, const float* __restrict__ vb) {
    int t = blockIdx.z;
    int bb = blockIdx.y;
    float* base = (t==0 ? g_K : t==1 ? g_Q : g_V) + bb*PER_B;
    const float* g = t==0 ? kg : t==1 ? qg : vg;
    const float* be = t==0 ? kb : t==1 ? qb : vb;
    int off = blockIdx.x*256 + threadIdx.x;
    float mu = g_mu[t*NB+bb], rv = g_rv[t*NB+bb];
    base[off] = (base[off] - mu) * rv * g[off] + be[off];
}

// ---------------- fused attention, TI2=60 rows/block, packed f32x2, occ 1 ----------------
// smem: a_t[596][68] ([col][row]), q_t[64][68], k_t[64][68]
__global__ __launch_bounds__(ATHR, 1) void attn_kernel(
    const float* __restrict__ qlw, const float* __restrict__ qlb,
    const float* __restrict__ klw, const float* __restrict__ klb,
    const float* __restrict__ alw, const float* __restrict__ alb) {
    extern __shared__ float smem[];
    float* a_t = smem;                     // [NPIX][APAD]  element [j][r]
    float* q_t = smem + NPIX*APAD;         // [DH][APAD]    element [d][r]
    float* k_t = q_t + DH*APAD;

    int tile = blockIdx.x, h = blockIdx.y, bb = blockIdx.z;
    int p0 = tile * TI2;
    int t = threadIdx.x;
    const float* Qb = g_Q + (bb*HEADS + h)*NPIX*DH;
    const float* Kb = g_K + (bb*HEADS + h)*NPIX*DH;
    const float* Vb = g_V + (bb*HEADS + h)*NPIX*DH;

    // load Q,K tile transposed: q_t[d][r], r in [0,60)
    for (int i = t; i < TI2*DH; i += ATHR) {
        int r = i % TI2, d = i / TI2;
        int p = p0 + r;
        q_t[d*APAD + r] = (p < NPIX) ? Qb[p*DH + d] : 0.f;
        k_t[d*APAD + r] = (p < NPIX) ? Kb[p*DH + d] : 0.f;
    }
    __syncthreads();

    // ---- A stage: logits -> elu -> a_t[j][r]. thread handles cols t and 320+t ----
    for (int c = 0; c < 2; c++) {
        int j = t + c*ATHR;
        if (j >= NPIX) break;
        unsigned long long acc[NRP];
        #pragma unroll
        for (int rp = 0; rp < NRP; rp++) acc[rp] = 0ull;
        #pragma unroll 4
        for (int d = 0; d < DH; d++) {
            unsigned long long qw2 = dup2(qlw[d*NPIX + j]);
            unsigned long long kw2 = dup2(klw[d*NPIX + j]);
            const unsigned long long* qp = (const unsigned long long*)(q_t + d*APAD);
            const unsigned long long* kp = (const unsigned long long*)(k_t + d*APAD);
            #pragma unroll
            for (int rp = 0; rp < NRP; rp++) {
                ffma2(acc[rp], qp[rp], qw2);
                ffma2(acc[rp], kp[rp], kw2);
            }
        }
        float bias = qlb[j] + klb[j];
        float2* arow = (float2*)(a_t + j*APAD);
        #pragma unroll
        for (int rp = 0; rp < NRP; rp++) {
            float2 o;
            o.x = eluf(lo2(acc[rp]) + bias);
            o.y = eluf(hi2(acc[rp]) + bias);
            arow[rp] = o;
        }
    }
    __syncthreads();

    // ---- S stage: S = A @ alin_w, cols j0=t, j1=320+t; distance-2 prefetch ----
    {
        int j0 = t, j1 = ATHR + t;
        bool has1 = (j1 < NPIX);
        int j1s = has1 ? j1 : j0;           // safe index for predicated-uniform code
        unsigned long long s0[NRP], s1[NRP];
        #pragma unroll
        for (int rp = 0; rp < NRP; rp++) { s0[rp] = 0ull; s1[rp] = 0ull; }

        float wa0 = alw[j0],          wb0 = alw[j1s];
        float wa1 = alw[NPIX + j0],   wb1 = alw[NPIX + j1s];
        for (int k = 0; k < NPIX; k += 2) {
            // prefetch k+2, k+3
            int k2 = (k + 2 < NPIX) ? k + 2 : 0;
            int k3 = (k + 3 < NPIX) ? k + 3 : 0;
            float na0 = alw[k2*NPIX + j0], nb0 = alw[k2*NPIX + j1s];
            float na1 = alw[k3*NPIX + j0], nb1 = alw[k3*NPIX + j1s];
            // iter k
            {
                const unsigned long long* ar = (const unsigned long long*)(a_t + k*APAD);
                unsigned long long w0 = dup2(wa0);
                unsigned long long w1 = dup2(wb0);
                #pragma unroll
                for (int rp = 0; rp < NRP; rp++) {
                    unsigned long long a = ar[rp];
                    ffma2(s0[rp], a, w0);
                    ffma2(s1[rp], a, w1);
                }
            }
            // iter k+1
            {
                const unsigned long long* ar = (const unsigned long long*)(a_t + (k+1)*APAD);
                unsigned long long w0 = dup2(wa1);
                unsigned long long w1 = dup2(wb1);
                #pragma unroll
                for (int rp = 0; rp < NRP; rp++) {
                    unsigned long long a = ar[rp];
                    ffma2(s0[rp], a, w0);
                    ffma2(s1[rp], a, w1);
                }
            }
            wa0 = na0; wb0 = nb0; wa1 = na1; wb1 = nb1;
        }
        __syncthreads();   // done reading a_t, safe to overwrite
        float b0 = alb[j0];
        float2* r0 = (float2*)(a_t + j0*APAD);
        #pragma unroll
        for (int rp = 0; rp < NRP; rp++) {
            float2 o; o.x = lo2(s0[rp]) + b0; o.y = hi2(s0[rp]) + b0;
            r0[rp] = o;
        }
        if (has1) {
            float b1 = alb[j1];
            float2* r1 = (float2*)(a_t + j1*APAD);
            #pragma unroll
            for (int rp = 0; rp < NRP; rp++) {
                float2 o; o.x = lo2(s1[rp]) + b1; o.y = hi2(s1[rp]) + b1;
                r1[rp] = o;
            }
        }
    }
    __syncthreads();

    // ---- softmax over cols, per row. 10 warps x 6 rows ----
    {
        int warp = t >> 5, lane = t & 31;
        #pragma unroll
        for (int i = 0; i < TI2/10; i++) {
            int r = warp + 10*i;
            float m = -1e30f;
            for (int j = lane; j < NPIX; j += 32) m = fmaxf(m, a_t[j*APAD + r]);
            #pragma unroll
            for (int o = 16; o; o >>= 1) m = fmaxf(m, __shfl_xor_sync(0xffffffffu, m, o));
            float sum = 0.f;
            for (int j = lane; j < NPIX; j += 32) {
                float e = __expf(a_t[j*APAD + r] - m);
                a_t[j*APAD + r] = e;
                sum += e;
            }
            #pragma unroll
            for (int o = 16; o; o >>= 1) sum += __shfl_xor_sync(0xffffffffu, sum, o);
            float inv = 1.f / sum;
            for (int j = lane; j < NPIX; j += 32) a_t[j*APAD + r] *= inv;
        }
    }
    __syncthreads();

    // ---- E stage: E = P @ V. thread = (d-pair dp = lane, row-group rg = warp) ----
    {
        int dp = t & 31, rg = t >> 5;           // rg in 0..9, rows rg+10q, q<6
        unsigned long long e[6];
        #pragma unroll
        for (int q = 0; q < 6; q++) e[q] = 0ull;
        for (int j = 0; j < NPIX; j++) {
            unsigned long long v = ((const unsigned long long*)(Vb + j*DH))[dp];
            #pragma unroll
            for (int q = 0; q < 6; q++) {
                unsigned long long a2 = dup2(a_t[j*APAD + rg + 10*q]);
                ffma2(e[q], v, a2);
            }
        }
        #pragma unroll
        for (int q = 0; q < 6; q++) {
            int p = p0 + rg + 10*q;
            if (p < NPIX) {
                float2 o; o.x = lo2(e[q]); o.y = hi2(e[q]);
                *(float2*)(g_E + (bb*NPIX + p)*256 + h*DH + 2*dp) = o;
            }
        }
    }
}

// ---------------- lin1 + relu ----------------
__global__ void lin1_kernel(const float* __restrict__ w, const float* __restrict__ b) {
    int idx = blockIdx.x * blockDim.x + threadIdx.x;
    if (idx >= NB*NPIX*DH) return;
    int d = idx & 63;
    int bp = idx >> 6;
    const float* e = g_E + bp*256;
    float acc = b[d];
    #pragma unroll 8
    for (int c = 0; c < 256; c++) acc += e[c] * w[c*DH + d];
    g_F[idx] = fmaxf(acc, 0.f);
}

// ---------------- LN2 stats (per b over 596*64, float accum) ----------------
__global__ void ln2_stats_kernel() {
    int bb = blockIdx.x;
    const float* base = g_F + bb*NPIX*DH;
    const int n = NPIX*DH;
    float s = 0.f, ss = 0.f;
    for (int i = threadIdx.x; i < n; i += blockDim.x) {
        float v = base[i]; s += v; ss += v*v;
    }
    __shared__ double sh[256], sh2[256];
    sh[threadIdx.x] = (double)s; sh2[threadIdx.x] = (double)ss; __syncthreads();
    for (int o = 128; o; o >>= 1) {
        if (threadIdx.x < o) { sh[threadIdx.x] += sh[threadIdx.x+o]; sh2[threadIdx.x] += sh2[threadIdx.x+o]; }
        __syncthreads();
    }
    if (threadIdx.x == 0) {
        double m = sh[0] / (double)n;
        double var = sh2[0] / (double)n - m*m;
        g_mu2[bb] = (float)m;
        g_rv2[bb] = (float)(1.0 / sqrt(var + 1e-5));
    }
}

// ---------------- LN2 apply + max over pixels ----------------
__global__ void ln2max_kernel() {
    int bb = blockIdx.x;
    int d = threadIdx.x & 63, pc = threadIdx.x >> 6;
    float mu = g_mu2[bb], rv = g_rv2[bb];
    float m = -1e30f;
    for (int p = pc; p < NPIX; p += 4) {
        float v = (g_F[(bb*NPIX + p)*DH + d] - mu) * rv;
        m = fmaxf(m, v);
    }
    __shared__ float sh[256];
    sh[threadIdx.x] = m; __syncthreads();
    if (pc == 0) {
        m = fmaxf(fmaxf(sh[d], sh[64+d]), fmaxf(sh[128+d], sh[192+d]));
        g_M[bb*DH + d] = m;
    }
}

// ---------------- final lin2 + elu ----------------
__global__ void final_kernel(const float* __restrict__ w, const float* __restrict__ b,
                             float* __restrict__ out) {
    int idx = blockIdx.x * blockDim.x + threadIdx.x;
    if (idx >= NB*10) return;
    int bb = idx / 10, j = idx % 10;
    float acc = b[j];
    #pragma unroll
    for (int d = 0; d < DH; d++) acc += g_M[bb*DH + d] * w[d*10 + j];
    out[idx] = eluf(acc);
}

extern "C" void kernel_launch(void* const* d_in, const int* in_sizes, int n_in,
                              void* d_out, int out_size) {
    const float* x       = (const float*)d_in[0];
    const float* conv1_w = (const float*)d_in[1];
    const float* conv1_b = (const float*)d_in[2];
    const float* conv2_w = (const float*)d_in[3];
    const float* conv2_b = (const float*)d_in[4];
    const float* kp_w    = (const float*)d_in[5];
    const float* kp_b    = (const float*)d_in[6];
    const float* qp_w    = (const float*)d_in[7];
    const float* qp_b    = (const float*)d_in[8];
    const float* vp_w    = (const float*)d_in[9];
    const float* vp_b    = (const float*)d_in[10];
    const float* klin_w  = (const float*)d_in[11];
    const float* klin_b  = (const float*)d_in[12];
    const float* qlin_w  = (const float*)d_in[13];
    const float* qlin_b  = (const float*)d_in[14];
    const float* alin_w  = (const float*)d_in[15];
    const float* alin_b  = (const float*)d_in[16];
    const float* knorm_g = (const float*)d_in[17];
    const float* knorm_b = (const float*)d_in[18];
    const float* qnorm_g = (const float*)d_in[19];
    const float* qnorm_b = (const float*)d_in[20];
    const float* vnorm_g = (const float*)d_in[21];
    const float* vnorm_b = (const float*)d_in[22];
    const float* lin1_w  = (const float*)d_in[23];
    const float* lin1_b  = (const float*)d_in[24];
    const float* lin2_w  = (const float*)d_in[25];
    const float* lin2_b  = (const float*)d_in[26];
    float* out = (float*)d_out;

    cudaFuncSetAttribute(attn_kernel, cudaFuncAttributeMaxDynamicSharedMemorySize, SMEM_BYTES);

    conv1_kernel<<<(NB*16*150*5 + 255)/256, 256>>>(x, conv1_w, conv1_b);
    conv2_feats_kernel<<<(NB*NPIX*34 + 255)/256, 256>>>(conv2_w, conv2_b);
    {
        dim3 g((NB*NPIX*256 + 255)/256, 3);
        proj_kernel<<<g, 256>>>(kp_w, kp_b, qp_w, qp_b, vp_w, vp_b);
    }
    {
        dim3 g(NB, 3);
        ln_stats_kernel<<<g, 256>>>();
    }
    {
        dim3 g(PER_B/256, NB, 3);
        ln_apply_kernel<<<g, 256>>>(knorm_g, knorm_b, qnorm_g, qnorm_b, vnorm_g, vnorm_b);
    }
    {
        dim3 g((NPIX + TI2 - 1)/TI2, HEADS, NB);  // (10, 4, 64)
        attn_kernel<<<g, ATHR, SMEM_BYTES>>>(qlin_w, qlin_b, klin_w, klin_b, alin_w, alin_b);
    }
    lin1_kernel<<<(NB*NPIX*DH + 255)/256, 256>>>(lin1_w, lin1_b);
    ln2_stats_kernel<<<NB, 256>>>();
    ln2max_kernel<<<NB, 256>>>();
    final_kernel<<<3, 256>>>(lin2_w, lin2_b, out);
}

// round 4
// speedup vs baseline: 1.2118x; 1.2118x over previous
#include <cuda_runtime.h>
#include <math.h>

#define NB 64
#define NPIX 596
#define HEADS 4
#define DH 64
#define PER_B (HEADS*NPIX*DH)   // 152576

#define TI2 32
#define NRP (TI2/2)             // 16 row-pairs
#define ATHR 320
#define APAD 36
#define SMEM_FLOATS (NPIX*APAD + 2*DH*APAD)   // 21456 + 4608 = 26064
#define SMEM_BYTES (SMEM_FLOATS*4)            // 104256

// ---------------- scratch (device globals, no allocation) ----------------
__device__ float g_conv1[NB*16*150*5];
__device__ float g_feats[NB*NPIX*34];
__device__ float g_K[NB*HEADS*NPIX*DH];
__device__ float g_Q[NB*HEADS*NPIX*DH];
__device__ float g_V[NB*HEADS*NPIX*DH];
__device__ float g_mu[3*NB], g_rv[3*NB];
__device__ float g_E[NB*NPIX*256];
__device__ float g_F[NB*NPIX*DH];
__device__ float g_mu2[NB], g_rv2[NB];
__device__ float g_M[NB*DH];

__device__ __forceinline__ float eluf(float x) {
    return x > 0.f ? x : (__expf(x) - 1.f);
}

// packed fp32x2 helpers (sm_103a)
__device__ __forceinline__ void ffma2(unsigned long long &acc,
                                      unsigned long long a,
                                      unsigned long long b) {
    asm("fma.rn.f32x2 %0, %1, %2, %0;" : "+l"(acc) : "l"(a), "l"(b));
}
__device__ __forceinline__ unsigned long long dup2(float x) {
    unsigned long long r;
    asm("mov.b64 %0, {%1, %1};" : "=l"(r) : "f"(x));
    return r;
}
__device__ __forceinline__ float lo2(unsigned long long v) {
    float a, b;
    asm("mov.b64 {%0, %1}, %2;" : "=f"(a), "=f"(b) : "l"(v));
    return a;
}
__device__ __forceinline__ float hi2(unsigned long long v) {
    float a, b;
    asm("mov.b64 {%0, %1}, %2;" : "=f"(a), "=f"(b) : "l"(v));
    return b;
}

// ---------------- conv1 + relu ----------------
__global__ void conv1_kernel(const float* __restrict__ x,
                             const float* __restrict__ w,
                             const float* __restrict__ b) {
    int idx = blockIdx.x * blockDim.x + threadIdx.x;
    if (idx >= NB*16*150*5) return;
    int ow = idx % 5;
    int oh = (idx / 5) % 150;
    int co = (idx / (5*150)) % 16;
    int bb = idx / (5*150*16);
    float acc = b[co];
    #pragma unroll
    for (int ci = 0; ci < 4; ci++)
        #pragma unroll
        for (int kh = 0; kh < 2; kh++)
            #pragma unroll
            for (int kw = 0; kw < 2; kw++)
                acc += x[((bb*4+ci)*151 + oh+kh)*6 + ow+kw] *
                       w[((co*4+ci)*2 + kh)*2 + kw];
    g_conv1[idx] = fmaxf(acc, 0.f);
}

// ---------------- conv2 + relu + coords -> feats (N, 596, 34) ----------------
__global__ void conv2_feats_kernel(const float* __restrict__ w,
                                   const float* __restrict__ b) {
    int idx = blockIdx.x * blockDim.x + threadIdx.x;
    if (idx >= NB*NPIX*34) return;
    int c = idx % 34;
    int p = (idx / 34) % NPIX;
    int bb = idx / (34*NPIX);
    int oh = p / 4, ow = p % 4;
    float val;
    if (c < 32) {
        float acc = b[c];
        #pragma unroll 4
        for (int ci = 0; ci < 16; ci++)
            #pragma unroll
            for (int kh = 0; kh < 2; kh++)
                #pragma unroll
                for (int kw = 0; kw < 2; kw++)
                    acc += g_conv1[((bb*16+ci)*150 + oh+kh)*5 + ow+kw] *
                           w[((c*16+ci)*2 + kh)*2 + kw];
        val = fmaxf(acc, 0.f);
    } else if (c == 32) {
        val = (float)ow / 4.f;
    } else {
        val = (float)oh / 149.f;
    }
    g_feats[idx] = val;
}

// ---------------- K/Q/V projections (b,p,hd) -> [b][h][p][d] ----------------
__global__ void proj_kernel(const float* __restrict__ kw, const float* __restrict__ kb,
                            const float* __restrict__ qw, const float* __restrict__ qb,
                            const float* __restrict__ vw, const float* __restrict__ vb) {
    int t = blockIdx.y;
    const float* W = t==0 ? kw : t==1 ? qw : vw;
    const float* B = t==0 ? kb : t==1 ? qb : vb;
    float* O = t==0 ? g_K : t==1 ? g_Q : g_V;
    int idx = blockIdx.x * blockDim.x + threadIdx.x;
    if (idx >= NB*NPIX*256) return;
    int hd = idx & 255;
    int bp = idx >> 8;
    int p = bp % NPIX, bb = bp / NPIX;
    const float* f = g_feats + bp*34;
    float acc = B[hd];
    #pragma unroll
    for (int c = 0; c < 34; c++) acc += f[c] * W[c*256 + hd];
    int h = hd >> 6, d = hd & 63;
    O[((bb*HEADS + h)*NPIX + p)*DH + d] = acc;
}

// ---------------- LN stats over (h,p,d) per batch (float accum) ----------------
__global__ void ln_stats_kernel() {
    int bb = blockIdx.x, t = blockIdx.y;
    const float* base = (t==0 ? g_K : t==1 ? g_Q : g_V) + bb*PER_B;
    float s = 0.f, ss = 0.f;
    for (int i = threadIdx.x; i < PER_B; i += blockDim.x) {
        float v = base[i]; s += v; ss += v*v;
    }
    __shared__ double sh[256], sh2[256];
    sh[threadIdx.x] = (double)s; sh2[threadIdx.x] = (double)ss; __syncthreads();
    for (int o = 128; o; o >>= 1) {
        if (threadIdx.x < o) { sh[threadIdx.x] += sh[threadIdx.x+o]; sh2[threadIdx.x] += sh2[threadIdx.x+o]; }
        __syncthreads();
    }
    if (threadIdx.x == 0) {
        double m = sh[0] / (double)PER_B;
        double var = sh2[0] / (double)PER_B - m*m;
        g_mu[t*NB+bb] = (float)m;
        g_rv[t*NB+bb] = (float)(1.0 / sqrt(var + 1e-5));
    }
}

// ---------------- LN apply (with affine g,b) in place ----------------
__global__ void ln_apply_kernel(const float* __restrict__ kg, const float* __restrict__ kb,
                                const float* __restrict__ qg, const float* __restrict__ qb,
                                const float* __restrict__ vg, const float* __restrict__ vb) {
    int t = blockIdx.z;
    int bb = blockIdx.y;
    float* base = (t==0 ? g_K : t==1 ? g_Q : g_V) + bb*PER_B;
    const float* g = t==0 ? kg : t==1 ? qg : vg;
    const float* be = t==0 ? kb : t==1 ? qb : vb;
    int off = blockIdx.x*256 + threadIdx.x;
    float mu = g_mu[t*NB+bb], rv = g_rv[t*NB+bb];
    base[off] = (base[off] - mu) * rv * g[off] + be[off];
}

// ---------------- fused attention, TI2=32 rows/block, packed f32x2, occ 2 ----------------
// smem: a_t[596][36] ([col][row]), q_t[64][36], k_t[64][36]
__global__ __launch_bounds__(ATHR, 2) void attn_kernel(
    const float* __restrict__ qlw, const float* __restrict__ qlb,
    const float* __restrict__ klw, const float* __restrict__ klb,
    const float* __restrict__ alw, const float* __restrict__ alb) {
    extern __shared__ float smem[];
    float* a_t = smem;                     // [NPIX][APAD]  element [j][r]
    float* q_t = smem + NPIX*APAD;         // [DH][APAD]    element [d][r]
    float* k_t = q_t + DH*APAD;

    int tile = blockIdx.x, h = blockIdx.y, bb = blockIdx.z;
    int p0 = tile * TI2;
    int t = threadIdx.x;
    const float* Qb = g_Q + (bb*HEADS + h)*NPIX*DH;
    const float* Kb = g_K + (bb*HEADS + h)*NPIX*DH;
    const float* Vb = g_V + (bb*HEADS + h)*NPIX*DH;

    // load Q,K tile transposed: q_t[d][r]
    for (int i = t; i < TI2*DH; i += ATHR) {
        int r = i >> 6, d = i & 63;
        int p = p0 + r;
        q_t[d*APAD + r] = (p < NPIX) ? Qb[p*DH + d] : 0.f;
        k_t[d*APAD + r] = (p < NPIX) ? Kb[p*DH + d] : 0.f;
    }
    __syncthreads();

    // ---- A stage: logits -> elu -> a_t[j][r]. thread handles cols t and 320+t ----
    for (int c = 0; c < 2; c++) {
        if (c == 1 && t >= NPIX - ATHR) break;   // t >= 276
        int j = c == 0 ? t : ATHR + t;
        unsigned long long acc[NRP];
        #pragma unroll
        for (int rp = 0; rp < NRP; rp++) acc[rp] = 0ull;
        #pragma unroll 4
        for (int d = 0; d < DH; d++) {
            unsigned long long qw2 = dup2(qlw[d*NPIX + j]);
            unsigned long long kw2 = dup2(klw[d*NPIX + j]);
            const unsigned long long* qp = (const unsigned long long*)(q_t + d*APAD);
            const unsigned long long* kp = (const unsigned long long*)(k_t + d*APAD);
            #pragma unroll
            for (int rp = 0; rp < NRP; rp++) {
                ffma2(acc[rp], qp[rp], qw2);
                ffma2(acc[rp], kp[rp], kw2);
            }
        }
        float bias = qlb[j] + klb[j];
        float2* arow = (float2*)(a_t + j*APAD);
        #pragma unroll
        for (int rp = 0; rp < NRP; rp++) {
            float2 o;
            o.x = eluf(lo2(acc[rp]) + bias);
            o.y = eluf(hi2(acc[rp]) + bias);
            arow[rp] = o;
        }
    }
    __syncthreads();

    // ---- S stage: S = A @ alin_w, cols j0=t, j1=320+t; group-2 sw pipeline ----
    {
        int j0 = t, j1 = ATHR + t;
        bool has1 = (j1 < NPIX);
        int j1s = has1 ? j1 : j0;
        unsigned long long s0[NRP], s1[NRP];
        #pragma unroll
        for (int rp = 0; rp < NRP; rp++) { s0[rp] = 0ull; s1[rp] = 0ull; }

        // prefetch group 0 (k = 0,1)
        float wa0 = alw[j0],        wb0 = alw[j1s];
        float wa1 = alw[NPIX + j0], wb1 = alw[NPIX + j1s];
        for (int k = 0; k < NPIX; k += 2) {
            // issue next-group loads before computing current group
            int k2 = (k + 2 < NPIX) ? k + 2 : 0;
            int k3 = (k + 3 < NPIX) ? k + 3 : 0;
            float na0 = alw[k2*NPIX + j0], nb0 = alw[k2*NPIX + j1s];
            float na1 = alw[k3*NPIX + j0], nb1 = alw[k3*NPIX + j1s];
            {
                const unsigned long long* ar = (const unsigned long long*)(a_t + k*APAD);
                unsigned long long w0 = dup2(wa0);
                unsigned long long w1 = dup2(wb0);
                #pragma unroll
                for (int rp = 0; rp < NRP; rp++) {
                    unsigned long long a = ar[rp];
                    ffma2(s0[rp], a, w0);
                    ffma2(s1[rp], a, w1);
                }
            }
            {
                const unsigned long long* ar = (const unsigned long long*)(a_t + (k+1)*APAD);
                unsigned long long w0 = dup2(wa1);
                unsigned long long w1 = dup2(wb1);
                #pragma unroll
                for (int rp = 0; rp < NRP; rp++) {
                    unsigned long long a = ar[rp];
                    ffma2(s0[rp], a, w0);
                    ffma2(s1[rp], a, w1);
                }
            }
            wa0 = na0; wb0 = nb0; wa1 = na1; wb1 = nb1;
        }
        __syncthreads();   // all a_s reads complete before overwrite
        float b0 = alb[j0];
        float2* r0 = (float2*)(a_t + j0*APAD);
        #pragma unroll
        for (int rp = 0; rp < NRP; rp++) {
            float2 o; o.x = lo2(s0[rp]) + b0; o.y = hi2(s0[rp]) + b0;
            r0[rp] = o;
        }
        if (has1) {
            float b1 = alb[j1];
            float2* r1 = (float2*)(a_t + j1*APAD);
            #pragma unroll
            for (int rp = 0; rp < NRP; rp++) {
                float2 o; o.x = lo2(s1[rp]) + b1; o.y = hi2(s1[rp]) + b1;
                r1[rp] = o;
            }
        }
    }
    __syncthreads();

    // ---- softmax over cols, per row. 10 warps cover 32 rows ----
    {
        int warp = t >> 5, lane = t & 31;
        for (int r = warp; r < TI2; r += 10) {
            float m = -1e30f;
            for (int j = lane; j < NPIX; j += 32) m = fmaxf(m, a_t[j*APAD + r]);
            #pragma unroll
            for (int o = 16; o; o >>= 1) m = fmaxf(m, __shfl_xor_sync(0xffffffffu, m, o));
            float sum = 0.f;
            for (int j = lane; j < NPIX; j += 32) {
                float e = __expf(a_t[j*APAD + r] - m);
                a_t[j*APAD + r] = e;
                sum += e;
            }
            #pragma unroll
            for (int o = 16; o; o >>= 1) sum += __shfl_xor_sync(0xffffffffu, sum, o);
            float inv = 1.f / sum;
            for (int j = lane; j < NPIX; j += 32) a_t[j*APAD + r] *= inv;
        }
    }
    __syncthreads();

    // ---- E stage: E = P @ V. thread = (d-pair dp = lane, row-group rg = warp) ----
    {
        int dp = t & 31, rg = t >> 5;           // rg in 0..9
        unsigned long long e[4] = {0ull, 0ull, 0ull, 0ull};
        int nr = (rg < 2) ? 4 : 3;              // rows rg + 10*q < 32
        for (int j = 0; j < NPIX; j++) {
            unsigned long long v = ((const unsigned long long*)(Vb + j*DH))[dp];
            #pragma unroll
            for (int q = 0; q < 4; q++) {
                if (q < nr) {
                    unsigned long long a2 = dup2(a_t[j*APAD + rg + 10*q]);
                    ffma2(e[q], v, a2);
                }
            }
        }
        #pragma unroll
        for (int q = 0; q < 4; q++) {
            if (q < nr) {
                int r = rg + 10*q;
                int p = p0 + r;
                if (p < NPIX) {
                    float2 o; o.x = lo2(e[q]); o.y = hi2(e[q]);
                    *(float2*)(g_E + (bb*NPIX + p)*256 + h*DH + 2*dp) = o;
                }
            }
        }
    }
}

// ---------------- lin1 + relu ----------------
__global__ void lin1_kernel(const float* __restrict__ w, const float* __restrict__ b) {
    int idx = blockIdx.x * blockDim.x + threadIdx.x;
    if (idx >= NB*NPIX*DH) return;
    int d = idx & 63;
    int bp = idx >> 6;
    const float* e = g_E + bp*256;
    float acc = b[d];
    #pragma unroll 8
    for (int c = 0; c < 256; c++) acc += e[c] * w[c*DH + d];
    g_F[idx] = fmaxf(acc, 0.f);
}

// ---------------- LN2 stats (per b over 596*64, float accum) ----------------
__global__ void ln2_stats_kernel() {
    int bb = blockIdx.x;
    const float* base = g_F + bb*NPIX*DH;
    const int n = NPIX*DH;
    float s = 0.f, ss = 0.f;
    for (int i = threadIdx.x; i < n; i += blockDim.x) {
        float v = base[i]; s += v; ss += v*v;
    }
    __shared__ double sh[256], sh2[256];
    sh[threadIdx.x] = (double)s; sh2[threadIdx.x] = (double)ss; __syncthreads();
    for (int o = 128; o; o >>= 1) {
        if (threadIdx.x < o) { sh[threadIdx.x] += sh[threadIdx.x+o]; sh2[threadIdx.x] += sh2[threadIdx.x+o]; }
        __syncthreads();
    }
    if (threadIdx.x == 0) {
        double m = sh[0] / (double)n;
        double var = sh2[0] / (double)n - m*m;
        g_mu2[bb] = (float)m;
        g_rv2[bb] = (float)(1.0 / sqrt(var + 1e-5));
    }
}

// ---------------- LN2 apply + max over pixels ----------------
__global__ void ln2max_kernel() {
    int bb = blockIdx.x;
    int d = threadIdx.x & 63, pc = threadIdx.x >> 6;
    float mu = g_mu2[bb], rv = g_rv2[bb];
    float m = -1e30f;
    for (int p = pc; p < NPIX; p += 4) {
        float v = (g_F[(bb*NPIX + p)*DH + d] - mu) * rv;
        m = fmaxf(m, v);
    }
    __shared__ float sh[256];
    sh[threadIdx.x] = m; __syncthreads();
    if (pc == 0) {
        m = fmaxf(fmaxf(sh[d], sh[64+d]), fmaxf(sh[128+d], sh[192+d]));
        g_M[bb*DH + d] = m;
    }
}

// ---------------- final lin2 + elu ----------------
__global__ void final_kernel(const float* __restrict__ w, const float* __restrict__ b,
                             float* __restrict__ out) {
    int idx = blockIdx.x * blockDim.x + threadIdx.x;
    if (idx >= NB*10) return;
    int bb = idx / 10, j = idx % 10;
    float acc = b[j];
    #pragma unroll
    for (int d = 0; d < DH; d++) acc += g_M[bb*DH + d] * w[d*10 + j];
    out[idx] = eluf(acc);
}

extern "C" void kernel_launch(void* const* d_in, const int* in_sizes, int n_in,
                              void* d_out, int out_size) {
    const float* x       = (const float*)d_in[0];
    const float* conv1_w = (const float*)d_in[1];
    const float* conv1_b = (const float*)d_in[2];
    const float* conv2_w = (const float*)d_in[3];
    const float* conv2_b = (const float*)d_in[4];
    const float* kp_w    = (const float*)d_in[5];
    const float* kp_b    = (const float*)d_in[6];
    const float* qp_w    = (const float*)d_in[7];
    const float* qp_b    = (const float*)d_in[8];
    const float* vp_w    = (const float*)d_in[9];
    const float* vp_b    = (const float*)d_in[10];
    const float* klin_w  = (const float*)d_in[11];
    const float* klin_b  = (const float*)d_in[12];
    const float* qlin_w  = (const float*)d_in[13];
    const float* qlin_b  = (const float*)d_in[14];
    const float* alin_w  = (const float*)d_in[15];
    const float* alin_b  = (const float*)d_in[16];
    const float* knorm_g = (const float*)d_in[17];
    const float* knorm_b = (const float*)d_in[18];
    const float* qnorm_g = (const float*)d_in[19];
    const float* qnorm_b = (const float*)d_in[20];
    const float* vnorm_g = (const float*)d_in[21];
    const float* vnorm_b = (const float*)d_in[22];
    const float* lin1_w  = (const float*)d_in[23];
    const float* lin1_b  = (const float*)d_in[24];
    const float* lin2_w  = (const float*)d_in[25];
    const float* lin2_b  = (const float*)d_in[26];
    float* out = (float*)d_out;

    cudaFuncSetAttribute(attn_kernel, cudaFuncAttributeMaxDynamicSharedMemorySize, SMEM_BYTES);

    conv1_kernel<<<(NB*16*150*5 + 255)/256, 256>>>(x, conv1_w, conv1_b);
    conv2_feats_kernel<<<(NB*NPIX*34 + 255)/256, 256>>>(conv2_w, conv2_b);
    {
        dim3 g((NB*NPIX*256 + 255)/256, 3);
        proj_kernel<<<g, 256>>>(kp_w, kp_b, qp_w, qp_b, vp_w, vp_b);
    }
    {
        dim3 g(NB, 3);
        ln_stats_kernel<<<g, 256>>>();
    }
    {
        dim3 g(PER_B/256, NB, 3);
        ln_apply_kernel<<<g, 256>>>(knorm_g, knorm_b, qnorm_g, qnorm_b, vnorm_g, vnorm_b);
    }
    {
        dim3 g((NPIX + TI2 - 1)/TI2, HEADS, NB);  // (19, 4, 64)
        attn_kernel<<<g, ATHR, SMEM_BYTES>>>(qlin_w, qlin_b, klin_w, klin_b, alin_w, alin_b);
    }
    lin1_kernel<<<(NB*NPIX*DH + 255)/256, 256>>>(lin1_w, lin1_b);
    ln2_stats_kernel<<<NB, 256>>>();
    ln2max_kernel<<<NB, 256>>>();
    final_kernel<<<3, 256>>>(lin2_w, lin2_b, out);
}

// round 6
// speedup vs baseline: 1.7331x; 1.4302x over previous
#include <cuda_runtime.h>
#include <cuda_bf16.h>
#include <math.h>
#include <stdint.h>

#define NB 64
#define NPIX 596
#define HEADS 4
#define DH 64
#define PER_B (HEADS*NPIX*DH)   // 152576
#define MROWS (NB*HEADS*NPIX)   // 152576 rows of A/S
#define KPAD 640                // padded K (and N) for GEMM

// ---- logits kernel config ----
#define LTI 32
#define LNRP (LTI/2)
#define LTHR 320
#define QPAD 36
#define AP 33
#define LOGITS_SMEM ((NPIX*AP + 2*DH*QPAD)*4)   // 97104

// ---- gemm config (mma.sync bf16) ----
#define GTHR 256
#define SK 72                                   // padded k-stride in bf16 elems
#define TILE_ELEMS (128*SK)                     // per matrix
#define GEMM_SMEM (4*TILE_ELEMS*2)              // 73728 bytes

// ---- E kernel config ----
#define EP 600
#define E_SMEM (32*EP*4)                        // 76800

// ---------------- scratch (device globals, no allocation) ----------------
__device__ float g_conv1[NB*16*150*5];
__device__ float g_feats[NB*NPIX*34];
__device__ float g_K[NB*HEADS*NPIX*DH];
__device__ float g_Q[NB*HEADS*NPIX*DH];
__device__ float g_V[NB*HEADS*NPIX*DH];
__device__ float g_mu[3*NB], g_rv[3*NB];
__device__ __nv_bfloat16 g_Ah[(size_t)MROWS*KPAD];
__device__ __nv_bfloat16 g_Al[(size_t)MROWS*KPAD];
__device__ __nv_bfloat16 g_Wh[(size_t)KPAD*KPAD];
__device__ __nv_bfloat16 g_Wl[(size_t)KPAD*KPAD];
__device__ float g_S[(size_t)MROWS*NPIX];
__device__ float g_E[(size_t)NB*NPIX*256];
__device__ float g_F[NB*NPIX*DH];
__device__ float g_mu2[NB], g_rv2[NB];
__device__ float g_M[NB*DH];

__device__ __forceinline__ float eluf(float x) {
    return x > 0.f ? x : (__expf(x) - 1.f);
}

// packed fp32x2 helpers (sm_103a)
__device__ __forceinline__ void ffma2(unsigned long long &acc,
                                      unsigned long long a,
                                      unsigned long long b) {
    asm("fma.rn.f32x2 %0, %1, %2, %0;" : "+l"(acc) : "l"(a), "l"(b));
}
__device__ __forceinline__ unsigned long long dup2(float x) {
    unsigned long long r;
    asm("mov.b64 %0, {%1, %1};" : "=l"(r) : "f"(x));
    return r;
}
__device__ __forceinline__ float lo2(unsigned long long v) {
    float a, b;
    asm("mov.b64 {%0, %1}, %2;" : "=f"(a), "=f"(b) : "l"(v));
    return a;
}
__device__ __forceinline__ float hi2(unsigned long long v) {
    float a, b;
    asm("mov.b64 {%0, %1}, %2;" : "=f"(a), "=f"(b) : "l"(v));
    return b;
}

// ---- mma.sync helpers (portable sm_80+ PTX; HMMA on Blackwell) ----
__device__ __forceinline__ void ldsm4(uint32_t* r, uint32_t addr) {
    asm volatile("ldmatrix.sync.aligned.m8n8.x4.shared.b16 {%0,%1,%2,%3}, [%4];"
        : "=r"(r[0]), "=r"(r[1]), "=r"(r[2]), "=r"(r[3]) : "r"(addr));
}
__device__ __forceinline__ void mma16816(float* c, const uint32_t* a,
                                         uint32_t b0, uint32_t b1) {
    asm volatile(
        "mma.sync.aligned.m16n8k16.row.col.f32.bf16.bf16.f32 "
        "{%0,%1,%2,%3}, {%4,%5,%6,%7}, {%8,%9}, {%0,%1,%2,%3};"
        : "+f"(c[0]), "+f"(c[1]), "+f"(c[2]), "+f"(c[3])
        : "r"(a[0]), "r"(a[1]), "r"(a[2]), "r"(a[3]), "r"(b0), "r"(b1));
}

// ---------------- conv1 + relu ----------------
__global__ void conv1_kernel(const float* __restrict__ x,
                             const float* __restrict__ w,
                             const float* __restrict__ b) {
    int idx = blockIdx.x * blockDim.x + threadIdx.x;
    if (idx >= NB*16*150*5) return;
    int ow = idx % 5;
    int oh = (idx / 5) % 150;
    int co = (idx / (5*150)) % 16;
    int bb = idx / (5*150*16);
    float acc = b[co];
    #pragma unroll
    for (int ci = 0; ci < 4; ci++)
        #pragma unroll
        for (int kh = 0; kh < 2; kh++)
            #pragma unroll
            for (int kw = 0; kw < 2; kw++)
                acc += x[((bb*4+ci)*151 + oh+kh)*6 + ow+kw] *
                       w[((co*4+ci)*2 + kh)*2 + kw];
    g_conv1[idx] = fmaxf(acc, 0.f);
}

// ---------------- conv2 + relu + coords -> feats ----------------
__global__ void conv2_feats_kernel(const float* __restrict__ w,
                                   const float* __restrict__ b) {
    int idx = blockIdx.x * blockDim.x + threadIdx.x;
    if (idx >= NB*NPIX*34) return;
    int c = idx % 34;
    int p = (idx / 34) % NPIX;
    int bb = idx / (34*NPIX);
    int oh = p / 4, ow = p % 4;
    float val;
    if (c < 32) {
        float acc = b[c];
        #pragma unroll 4
        for (int ci = 0; ci < 16; ci++)
            #pragma unroll
            for (int kh = 0; kh < 2; kh++)
                #pragma unroll
                for (int kw = 0; kw < 2; kw++)
                    acc += g_conv1[((bb*16+ci)*150 + oh+kh)*5 + ow+kw] *
                           w[((c*16+ci)*2 + kh)*2 + kw];
        val = fmaxf(acc, 0.f);
    } else if (c == 32) {
        val = (float)ow / 4.f;
    } else {
        val = (float)oh / 149.f;
    }
    g_feats[idx] = val;
}

// ---------------- K/Q/V projections ----------------
__global__ void proj_kernel(const float* __restrict__ kw, const float* __restrict__ kb,
                            const float* __restrict__ qw, const float* __restrict__ qb,
                            const float* __restrict__ vw, const float* __restrict__ vb) {
    int t = blockIdx.y;
    const float* W = t==0 ? kw : t==1 ? qw : vw;
    const float* B = t==0 ? kb : t==1 ? qb : vb;
    float* O = t==0 ? g_K : t==1 ? g_Q : g_V;
    int idx = blockIdx.x * blockDim.x + threadIdx.x;
    if (idx >= NB*NPIX*256) return;
    int hd = idx & 255;
    int bp = idx >> 8;
    int p = bp % NPIX, bb = bp / NPIX;
    const float* f = g_feats + bp*34;
    float acc = B[hd];
    #pragma unroll
    for (int c = 0; c < 34; c++) acc += f[c] * W[c*256 + hd];
    int h = hd >> 6, d = hd & 63;
    O[((bb*HEADS + h)*NPIX + p)*DH + d] = acc;
}

// ---------------- LN stats ----------------
__global__ void ln_stats_kernel() {
    int bb = blockIdx.x, t = blockIdx.y;
    const float* base = (t==0 ? g_K : t==1 ? g_Q : g_V) + bb*PER_B;
    float s = 0.f, ss = 0.f;
    for (int i = threadIdx.x; i < PER_B; i += blockDim.x) {
        float v = base[i]; s += v; ss += v*v;
    }
    __shared__ double sh[256], sh2[256];
    sh[threadIdx.x] = (double)s; sh2[threadIdx.x] = (double)ss; __syncthreads();
    for (int o = 128; o; o >>= 1) {
        if (threadIdx.x < o) { sh[threadIdx.x] += sh[threadIdx.x+o]; sh2[threadIdx.x] += sh2[threadIdx.x+o]; }
        __syncthreads();
    }
    if (threadIdx.x == 0) {
        double m = sh[0] / (double)PER_B;
        double var = sh2[0] / (double)PER_B - m*m;
        g_mu[t*NB+bb] = (float)m;
        g_rv[t*NB+bb] = (float)(1.0 / sqrt(var + 1e-5));
    }
}

// ---------------- LN apply ----------------
__global__ void ln_apply_kernel(const float* __restrict__ kg, const float* __restrict__ kb,
                                const float* __restrict__ qg, const float* __restrict__ qb,
                                const float* __restrict__ vg, const float* __restrict__ vb) {
    int t = blockIdx.z;
    int bb = blockIdx.y;
    float* base = (t==0 ? g_K : t==1 ? g_Q : g_V) + bb*PER_B;
    const float* g = t==0 ? kg : t==1 ? qg : vg;
    const float* be = t==0 ? kb : t==1 ? qb : vb;
    int off = blockIdx.x*256 + threadIdx.x;
    float mu = g_mu[t*NB+bb], rv = g_rv[t*NB+bb];
    base[off] = (base[off] - mu) * rv * g[off] + be[off];
}

// ---------------- prep: Wt hi/lo = transpose(alin_w) bf16, zero-padded ----------------
__global__ void prepw_kernel(const float* __restrict__ alw) {
    int idx = blockIdx.x*256 + threadIdx.x;
    if (idx >= KPAD*KPAD) return;
    int k = idx / KPAD, n = idx % KPAD;
    float v = (k < NPIX && n < NPIX) ? alw[k*NPIX + n] : 0.f;
    __nv_bfloat16 h = __float2bfloat16(v);
    g_Wh[(size_t)n*KPAD + k] = h;
    g_Wl[(size_t)n*KPAD + k] = __float2bfloat16(v - __bfloat162float(h));
}

// ---------------- logits: A = elu(Q@qlw + K@klw + b) -> bf16 hi/lo global ----------------
__global__ __launch_bounds__(LTHR, 2) void logits_kernel(
    const float* __restrict__ qlw, const float* __restrict__ qlb,
    const float* __restrict__ klw, const float* __restrict__ klb) {
    extern __shared__ float smemf[];
    float* a_t = smemf;                     // [NPIX][AP]
    float* q_t = smemf + NPIX*AP;           // [DH][QPAD]
    float* k_t = q_t + DH*QPAD;

    int tile = blockIdx.x, h = blockIdx.y, bb = blockIdx.z;
    int p0 = tile * LTI;
    int t = threadIdx.x;
    int bh = bb*HEADS + h;
    const float* Qb = g_Q + (size_t)bh*NPIX*DH;
    const float* Kb = g_K + (size_t)bh*NPIX*DH;

    for (int i = t; i < LTI*DH; i += LTHR) {
        int r = i >> 6, d = i & 63;
        int p = p0 + r;
        q_t[d*QPAD + r] = (p < NPIX) ? Qb[p*DH + d] : 0.f;
        k_t[d*QPAD + r] = (p < NPIX) ? Kb[p*DH + d] : 0.f;
    }
    __syncthreads();

    for (int c = 0; c < 2; c++) {
        if (c == 1 && t >= NPIX - LTHR) break;
        int j = c == 0 ? t : LTHR + t;
        unsigned long long acc[LNRP];
        #pragma unroll
        for (int rp = 0; rp < LNRP; rp++) acc[rp] = 0ull;
        #pragma unroll 4
        for (int d = 0; d < DH; d++) {
            unsigned long long qw2 = dup2(qlw[d*NPIX + j]);
            unsigned long long kw2 = dup2(klw[d*NPIX + j]);
            const unsigned long long* qp = (const unsigned long long*)(q_t + d*QPAD);
            const unsigned long long* kp = (const unsigned long long*)(k_t + d*QPAD);
            #pragma unroll
            for (int rp = 0; rp < LNRP; rp++) {
                ffma2(acc[rp], qp[rp], qw2);
                ffma2(acc[rp], kp[rp], kw2);
            }
        }
        float bias = qlb[j] + klb[j];
        #pragma unroll
        for (int rp = 0; rp < LNRP; rp++) {
            a_t[j*AP + 2*rp]     = eluf(lo2(acc[rp]) + bias);
            a_t[j*AP + 2*rp + 1] = eluf(hi2(acc[rp]) + bias);
        }
    }
    __syncthreads();

    // coalesced write-out as bf16 hi/lo pairs; zero pad cols 596..639
    for (int r = 0; r < LTI; r++) {
        int p = p0 + r;
        if (p >= NPIX) break;
        int j = 2*t;                          // 0..638
        float a0 = (j < NPIX)   ? a_t[j*AP + r]     : 0.f;
        float a1 = (j+1 < NPIX) ? a_t[(j+1)*AP + r] : 0.f;
        __nv_bfloat16 h0 = __float2bfloat16(a0);
        __nv_bfloat16 h1 = __float2bfloat16(a1);
        __nv_bfloat16 l0 = __float2bfloat16(a0 - __bfloat162float(h0));
        __nv_bfloat16 l1 = __float2bfloat16(a1 - __bfloat162float(h1));
        size_t base = ((size_t)bh*NPIX + p)*KPAD + j;
        __nv_bfloat162 ph; ph.x = h0; ph.y = h1;
        __nv_bfloat162 pl; pl.x = l0; pl.y = l1;
        *(__nv_bfloat162*)(g_Ah + base) = ph;
        *(__nv_bfloat162*)(g_Al + base) = pl;
    }
}

// ---------------- GEMM via mma.sync: S = Ah@Wh^T + Ah@Wl^T + Al@Wh^T (+ alb) ----------------
__device__ __forceinline__ void load_tile16(__nv_bfloat16* dst,
                                            const __nv_bfloat16* g, int row0, int kc,
                                            int tid) {
    #pragma unroll
    for (int j = 0; j < 4; j++) {
        int idx = tid + j*GTHR;              // 0..1023
        int r = idx >> 3, q = idx & 7;
        *(uint4*)(dst + r*SK + q*8) =
            *(const uint4*)(g + (size_t)(row0 + r)*KPAD + kc + q*8);
    }
}

__global__ __launch_bounds__(GTHR, 2) void gemm_kernel(const float* __restrict__ alb) {
    extern __shared__ __nv_bfloat16 gsm[];
    __nv_bfloat16* sAh = gsm;
    __nv_bfloat16* sAl = gsm + TILE_ELEMS;
    __nv_bfloat16* sWh = gsm + 2*TILE_ELEMS;
    __nv_bfloat16* sWl = gsm + 3*TILE_ELEMS;

    int tid = threadIdx.x;
    int lane = tid & 31;
    int wid = tid >> 5;
    int wm = wid & 3;                        // 0..3 (32 rows each)
    int wn = wid >> 2;                       // 0..1 (64 cols each)
    int n0 = blockIdx.x * 128;
    int m0 = blockIdx.y * 128;

    float acc[2][8][4];
    #pragma unroll
    for (int mi = 0; mi < 2; mi++)
        #pragma unroll
        for (int ni = 0; ni < 8; ni++)
            #pragma unroll
            for (int k = 0; k < 4; k++) acc[mi][ni][k] = 0.f;

    // ldmatrix lane addressing
    int lr = lane & 15;                      // row within 16
    int lc = (lane >> 4) * 8;                // 0 or 8 (k-offset)

    for (int ch = 0; ch < 10; ch++) {
        int kc = ch * 64;
        load_tile16(sAh, g_Ah, m0, kc, tid);
        load_tile16(sAl, g_Al, m0, kc, tid);
        load_tile16(sWh, g_Wh, n0, kc, tid);
        load_tile16(sWl, g_Wl, n0, kc, tid);
        __syncthreads();

        #pragma unroll
        for (int ks = 0; ks < 4; ks++) {
            int col = ks*16 + lc;
            uint32_t ah[2][4], al[2][4];
            #pragma unroll
            for (int mi = 0; mi < 2; mi++) {
                int row = wm*32 + mi*16 + lr;
                ldsm4(ah[mi], (uint32_t)__cvta_generic_to_shared(sAh + row*SK + col));
                ldsm4(al[mi], (uint32_t)__cvta_generic_to_shared(sAl + row*SK + col));
            }
            #pragma unroll
            for (int nb = 0; nb < 4; nb++) {
                int nrow = wn*64 + nb*16 + lr;
                uint32_t bh[4], bl[4];
                ldsm4(bh, (uint32_t)__cvta_generic_to_shared(sWh + nrow*SK + col));
                ldsm4(bl, (uint32_t)__cvta_generic_to_shared(sWl + nrow*SK + col));
                #pragma unroll
                for (int mi = 0; mi < 2; mi++) {
                    mma16816(acc[mi][2*nb],   ah[mi], bh[0], bh[2]);
                    mma16816(acc[mi][2*nb+1], ah[mi], bh[1], bh[3]);
                    mma16816(acc[mi][2*nb],   ah[mi], bl[0], bl[2]);
                    mma16816(acc[mi][2*nb+1], ah[mi], bl[1], bl[3]);
                    mma16816(acc[mi][2*nb],   al[mi], bh[0], bh[2]);
                    mma16816(acc[mi][2*nb+1], al[mi], bh[1], bh[3]);
                }
            }
        }
        __syncthreads();
    }

    // epilogue: C[m][n] + alb[n] -> g_S
    #pragma unroll
    for (int mi = 0; mi < 2; mi++) {
        #pragma unroll
        for (int ni = 0; ni < 8; ni++) {
            int n = n0 + wn*64 + ni*8 + (lane & 3)*2;
            #pragma unroll
            for (int half = 0; half < 2; half++) {
                int m = m0 + wm*32 + mi*16 + (lane >> 2) + half*8;
                if (n + 1 < NPIX) {
                    float2 o;
                    o.x = acc[mi][ni][2*half]   + alb[n];
                    o.y = acc[mi][ni][2*half+1] + alb[n+1];
                    *(float2*)(g_S + (size_t)m*NPIX + n) = o;
                } else if (n < NPIX) {
                    g_S[(size_t)m*NPIX + n] = acc[mi][ni][2*half] + alb[n];
                }
            }
        }
    }
}

// ---------------- softmax (in-place on g_S), warp per row ----------------
__global__ __launch_bounds__(256) void softmax_kernel() {
    int row = blockIdx.x*8 + (threadIdx.x >> 5);
    int lane = threadIdx.x & 31;
    float* S = g_S + (size_t)row*NPIX;
    float v[19];
    float m = -1e30f;
    #pragma unroll
    for (int i = 0; i < 19; i++) {
        int j = lane + 32*i;
        v[i] = (j < NPIX) ? S[j] : -1e30f;
        m = fmaxf(m, v[i]);
    }
    #pragma unroll
    for (int o = 16; o; o >>= 1) m = fmaxf(m, __shfl_xor_sync(0xffffffffu, m, o));
    float s = 0.f;
    #pragma unroll
    for (int i = 0; i < 19; i++) {
        v[i] = __expf(v[i] - m);
        s += v[i];
    }
    #pragma unroll
    for (int o = 16; o; o >>= 1) s += __shfl_xor_sync(0xffffffffu, s, o);
    float inv = 1.f / s;
    #pragma unroll
    for (int i = 0; i < 19; i++) {
        int j = lane + 32*i;
        if (j < NPIX) S[j] = v[i]*inv;
    }
}

// ---------------- E = P @ V ----------------
__global__ __launch_bounds__(256, 2) void e_kernel() {
    extern __shared__ float p_s[];          // [32][EP]
    int tile = blockIdx.x, h = blockIdx.y, bb = blockIdx.z;
    int p0 = tile * 32;
    int t = threadIdx.x;
    int bh = bb*HEADS + h;
    const float* Vb = g_V + (size_t)bh*NPIX*DH;

    for (int r = 0; r < 32; r++) {
        int p = p0 + r;
        if (p < NPIX) {
            const float* src = g_S + ((size_t)bh*NPIX + p)*NPIX;
            for (int j = t; j < NPIX; j += 256) p_s[r*EP + j] = src[j];
        } else {
            for (int j = t; j < NPIX; j += 256) p_s[r*EP + j] = 0.f;
        }
    }
    __syncthreads();

    int dp = t & 31, rg = t >> 5;           // rg in 0..7, rows rg+8q
    unsigned long long e[4] = {0ull, 0ull, 0ull, 0ull};
    for (int j = 0; j < NPIX; j++) {
        unsigned long long v = *(const unsigned long long*)(Vb + j*DH + 2*dp);
        #pragma unroll
        for (int q = 0; q < 4; q++)
            ffma2(e[q], v, dup2(p_s[(rg + 8*q)*EP + j]));
    }
    #pragma unroll
    for (int q = 0; q < 4; q++) {
        int p = p0 + rg + 8*q;
        if (p < NPIX) {
            float2 o; o.x = lo2(e[q]); o.y = hi2(e[q]);
            *(float2*)(g_E + ((size_t)bb*NPIX + p)*256 + h*DH + 2*dp) = o;
        }
    }
}

// ---------------- lin1 + relu ----------------
__global__ void lin1_kernel(const float* __restrict__ w, const float* __restrict__ b) {
    int idx = blockIdx.x * blockDim.x + threadIdx.x;
    if (idx >= NB*NPIX*DH) return;
    int d = idx & 63;
    int bp = idx >> 6;
    const float* e = g_E + (size_t)bp*256;
    float acc = b[d];
    #pragma unroll 8
    for (int c = 0; c < 256; c++) acc += e[c] * w[c*DH + d];
    g_F[idx] = fmaxf(acc, 0.f);
}

// ---------------- LN2 stats ----------------
__global__ void ln2_stats_kernel() {
    int bb = blockIdx.x;
    const float* base = g_F + bb*NPIX*DH;
    const int n = NPIX*DH;
    float s = 0.f, ss = 0.f;
    for (int i = threadIdx.x; i < n; i += blockDim.x) {
        float v = base[i]; s += v; ss += v*v;
    }
    __shared__ double sh[256], sh2[256];
    sh[threadIdx.x] = (double)s; sh2[threadIdx.x] = (double)ss; __syncthreads();
    for (int o = 128; o; o >>= 1) {
        if (threadIdx.x < o) { sh[threadIdx.x] += sh[threadIdx.x+o]; sh2[threadIdx.x] += sh2[threadIdx.x+o]; }
        __syncthreads();
    }
    if (threadIdx.x == 0) {
        double m = sh[0] / (double)n;
        double var = sh2[0] / (double)n - m*m;
        g_mu2[bb] = (float)m;
        g_rv2[bb] = (float)(1.0 / sqrt(var + 1e-5));
    }
}

// ---------------- LN2 apply + max ----------------
__global__ void ln2max_kernel() {
    int bb = blockIdx.x;
    int d = threadIdx.x & 63, pc = threadIdx.x >> 6;
    float mu = g_mu2[bb], rv = g_rv2[bb];
    float m = -1e30f;
    for (int p = pc; p < NPIX; p += 4) {
        float v = (g_F[(bb*NPIX + p)*DH + d] - mu) * rv;
        m = fmaxf(m, v);
    }
    __shared__ float sh[256];
    sh[threadIdx.x] = m; __syncthreads();
    if (pc == 0) {
        m = fmaxf(fmaxf(sh[d], sh[64+d]), fmaxf(sh[128+d], sh[192+d]));
        g_M[bb*DH + d] = m;
    }
}

// ---------------- final lin2 + elu ----------------
__global__ void final_kernel(const float* __restrict__ w, const float* __restrict__ b,
                             float* __restrict__ out) {
    int idx = blockIdx.x * blockDim.x + threadIdx.x;
    if (idx >= NB*10) return;
    int bb = idx / 10, j = idx % 10;
    float acc = b[j];
    #pragma unroll
    for (int d = 0; d < DH; d++) acc += g_M[bb*DH + d] * w[d*10 + j];
    out[idx] = eluf(acc);
}

extern "C" void kernel_launch(void* const* d_in, const int* in_sizes, int n_in,
                              void* d_out, int out_size) {
    const float* x       = (const float*)d_in[0];
    const float* conv1_w = (const float*)d_in[1];
    const float* conv1_b = (const float*)d_in[2];
    const float* conv2_w = (const float*)d_in[3];
    const float* conv2_b = (const float*)d_in[4];
    const float* kp_w    = (const float*)d_in[5];
    const float* kp_b    = (const float*)d_in[6];
    const float* qp_w    = (const float*)d_in[7];
    const float* qp_b    = (const float*)d_in[8];
    const float* vp_w    = (const float*)d_in[9];
    const float* vp_b    = (const float*)d_in[10];
    const float* klin_w  = (const float*)d_in[11];
    const float* klin_b  = (const float*)d_in[12];
    const float* qlin_w  = (const float*)d_in[13];
    const float* qlin_b  = (const float*)d_in[14];
    const float* alin_w  = (const float*)d_in[15];
    const float* alin_b  = (const float*)d_in[16];
    const float* knorm_g = (const float*)d_in[17];
    const float* knorm_b = (const float*)d_in[18];
    const float* qnorm_g = (const float*)d_in[19];
    const float* qnorm_b = (const float*)d_in[20];
    const float* vnorm_g = (const float*)d_in[21];
    const float* vnorm_b = (const float*)d_in[22];
    const float* lin1_w  = (const float*)d_in[23];
    const float* lin1_b  = (const float*)d_in[24];
    const float* lin2_w  = (const float*)d_in[25];
    const float* lin2_b  = (const float*)d_in[26];
    float* out = (float*)d_out;

    cudaFuncSetAttribute(logits_kernel, cudaFuncAttributeMaxDynamicSharedMemorySize, LOGITS_SMEM);
    cudaFuncSetAttribute(gemm_kernel,   cudaFuncAttributeMaxDynamicSharedMemorySize, GEMM_SMEM);
    cudaFuncSetAttribute(e_kernel,      cudaFuncAttributeMaxDynamicSharedMemorySize, E_SMEM);

    conv1_kernel<<<(NB*16*150*5 + 255)/256, 256>>>(x, conv1_w, conv1_b);
    conv2_feats_kernel<<<(NB*NPIX*34 + 255)/256, 256>>>(conv2_w, conv2_b);
    {
        dim3 g((NB*NPIX*256 + 255)/256, 3);
        proj_kernel<<<g, 256>>>(kp_w, kp_b, qp_w, qp_b, vp_w, vp_b);
    }
    {
        dim3 g(NB, 3);
        ln_stats_kernel<<<g, 256>>>();
    }
    {
        dim3 g(PER_B/256, NB, 3);
        ln_apply_kernel<<<g, 256>>>(knorm_g, knorm_b, qnorm_g, qnorm_b, vnorm_g, vnorm_b);
    }
    prepw_kernel<<<(KPAD*KPAD + 255)/256, 256>>>(alin_w);
    {
        dim3 g((NPIX + LTI - 1)/LTI, HEADS, NB);   // (19, 4, 64)
        logits_kernel<<<g, LTHR, LOGITS_SMEM>>>(qlin_w, qlin_b, klin_w, klin_b);
    }
    {
        dim3 g(KPAD/128, MROWS/128);               // (5, 1192): n fastest for A-tile L2 reuse
        gemm_kernel<<<g, GTHR, GEMM_SMEM>>>(alin_b);
    }
    softmax_kernel<<<MROWS/8, 256>>>();
    {
        dim3 g((NPIX + 31)/32, HEADS, NB);         // (19, 4, 64)
        e_kernel<<<g, 256, E_SMEM>>>();
    }
    lin1_kernel<<<(NB*NPIX*DH + 255)/256, 256>>>(lin1_w, lin1_b);
    ln2_stats_kernel<<<NB, 256>>>();
    ln2max_kernel<<<NB, 256>>>();
    final_kernel<<<3, 256>>>(lin2_w, lin2_b, out);
}

// round 7
// speedup vs baseline: 2.5003x; 1.4427x over previous
#include <cuda_runtime.h>
#include <cuda_bf16.h>
#include <math.h>
#include <stdint.h>

#define NB 64
#define NPIX 596
#define HEADS 4
#define DH 64
#define PER_B (HEADS*NPIX*DH)   // 152576
#define MROWS (NB*HEADS*NPIX)   // 152576
#define KPAD 640

// ---- gemm common ----
#define GTHR 256
#define SK 72
#define TILE_ELEMS (128*SK)
#define GEMM_SMEM (4*TILE_ELEMS*2)              // 73728
// e-gemm smem: P 128xSK hi/lo + V 64xSK hi/lo
#define EGEMM_SMEM ((2*128*SK + 2*64*SK)*2)     // 55296

// ---------------- scratch ----------------
__device__ float g_conv1[NB*16*150*5];
__device__ float g_feats[NB*NPIX*34];
__device__ float g_K[NB*HEADS*NPIX*DH];
__device__ float g_Q[NB*HEADS*NPIX*DH];
__device__ float g_V[NB*HEADS*NPIX*DH];
__device__ float g_mu[3*NB], g_rv[3*NB];
__device__ __nv_bfloat16 g_QKh[(size_t)MROWS*128];
__device__ __nv_bfloat16 g_QKl[(size_t)MROWS*128];
__device__ __nv_bfloat16 g_Wqkh[(size_t)KPAD*128];
__device__ __nv_bfloat16 g_Wqkl[(size_t)KPAD*128];
__device__ __nv_bfloat16 g_Ah[(size_t)MROWS*KPAD];   // logits A, then P after softmax
__device__ __nv_bfloat16 g_Al[(size_t)MROWS*KPAD];
__device__ __nv_bfloat16 g_Wh[(size_t)KPAD*KPAD];
__device__ __nv_bfloat16 g_Wl[(size_t)KPAD*KPAD];
__device__ __nv_bfloat16 g_Vth[(size_t)NB*HEADS*DH*KPAD];
__device__ __nv_bfloat16 g_Vtl[(size_t)NB*HEADS*DH*KPAD];
__device__ float g_S[(size_t)MROWS*NPIX];
__device__ float g_E[(size_t)NB*NPIX*256];
__device__ float g_F[NB*NPIX*DH];
__device__ float g_mu2[NB], g_rv2[NB];
__device__ float g_M[NB*DH];

__device__ __forceinline__ float eluf(float x) {
    return x > 0.f ? x : (__expf(x) - 1.f);
}

// ---- mma.sync helpers (sm_80+ PTX) ----
__device__ __forceinline__ void ldsm4(uint32_t* r, uint32_t addr) {
    asm volatile("ldmatrix.sync.aligned.m8n8.x4.shared.b16 {%0,%1,%2,%3}, [%4];"
        : "=r"(r[0]), "=r"(r[1]), "=r"(r[2]), "=r"(r[3]) : "r"(addr));
}
__device__ __forceinline__ void mma16816(float* c, const uint32_t* a,
                                         uint32_t b0, uint32_t b1) {
    asm volatile(
        "mma.sync.aligned.m16n8k16.row.col.f32.bf16.bf16.f32 "
        "{%0,%1,%2,%3}, {%4,%5,%6,%7}, {%8,%9}, {%0,%1,%2,%3};"
        : "+f"(c[0]), "+f"(c[1]), "+f"(c[2]), "+f"(c[3])
        : "r"(a[0]), "r"(a[1]), "r"(a[2]), "r"(a[3]), "r"(b0), "r"(b1));
}

// ---------------- conv1 + relu ----------------
__global__ void conv1_kernel(const float* __restrict__ x,
                             const float* __restrict__ w,
                             const float* __restrict__ b) {
    int idx = blockIdx.x * blockDim.x + threadIdx.x;
    if (idx >= NB*16*150*5) return;
    int ow = idx % 5;
    int oh = (idx / 5) % 150;
    int co = (idx / (5*150)) % 16;
    int bb = idx / (5*150*16);
    float acc = b[co];
    #pragma unroll
    for (int ci = 0; ci < 4; ci++)
        #pragma unroll
        for (int kh = 0; kh < 2; kh++)
            #pragma unroll
            for (int kw = 0; kw < 2; kw++)
                acc += x[((bb*4+ci)*151 + oh+kh)*6 + ow+kw] *
                       w[((co*4+ci)*2 + kh)*2 + kw];
    g_conv1[idx] = fmaxf(acc, 0.f);
}

// ---------------- conv2 + relu + coords -> feats ----------------
__global__ void conv2_feats_kernel(const float* __restrict__ w,
                                   const float* __restrict__ b) {
    int idx = blockIdx.x * blockDim.x + threadIdx.x;
    if (idx >= NB*NPIX*34) return;
    int c = idx % 34;
    int p = (idx / 34) % NPIX;
    int bb = idx / (34*NPIX);
    int oh = p / 4, ow = p % 4;
    float val;
    if (c < 32) {
        float acc = b[c];
        #pragma unroll 4
        for (int ci = 0; ci < 16; ci++)
            #pragma unroll
            for (int kh = 0; kh < 2; kh++)
                #pragma unroll
                for (int kw = 0; kw < 2; kw++)
                    acc += g_conv1[((bb*16+ci)*150 + oh+kh)*5 + ow+kw] *
                           w[((c*16+ci)*2 + kh)*2 + kw];
        val = fmaxf(acc, 0.f);
    } else if (c == 32) {
        val = (float)ow / 4.f;
    } else {
        val = (float)oh / 149.f;
    }
    g_feats[idx] = val;
}

// ---------------- K/Q/V projections ----------------
__global__ void proj_kernel(const float* __restrict__ kw, const float* __restrict__ kb,
                            const float* __restrict__ qw, const float* __restrict__ qb,
                            const float* __restrict__ vw, const float* __restrict__ vb) {
    int t = blockIdx.y;
    const float* W = t==0 ? kw : t==1 ? qw : vw;
    const float* B = t==0 ? kb : t==1 ? qb : vb;
    float* O = t==0 ? g_K : t==1 ? g_Q : g_V;
    int idx = blockIdx.x * blockDim.x + threadIdx.x;
    if (idx >= NB*NPIX*256) return;
    int hd = idx & 255;
    int bp = idx >> 8;
    int p = bp % NPIX, bb = bp / NPIX;
    const float* f = g_feats + bp*34;
    float acc = B[hd];
    #pragma unroll
    for (int c = 0; c < 34; c++) acc += f[c] * W[c*256 + hd];
    int h = hd >> 6, d = hd & 63;
    O[((bb*HEADS + h)*NPIX + p)*DH + d] = acc;
}

// ---------------- LN stats ----------------
__global__ void ln_stats_kernel() {
    int bb = blockIdx.x, t = blockIdx.y;
    const float* base = (t==0 ? g_K : t==1 ? g_Q : g_V) + bb*PER_B;
    float s = 0.f, ss = 0.f;
    for (int i = threadIdx.x; i < PER_B; i += blockDim.x) {
        float v = base[i]; s += v; ss += v*v;
    }
    __shared__ double sh[256], sh2[256];
    sh[threadIdx.x] = (double)s; sh2[threadIdx.x] = (double)ss; __syncthreads();
    for (int o = 128; o; o >>= 1) {
        if (threadIdx.x < o) { sh[threadIdx.x] += sh[threadIdx.x+o]; sh2[threadIdx.x] += sh2[threadIdx.x+o]; }
        __syncthreads();
    }
    if (threadIdx.x == 0) {
        double m = sh[0] / (double)PER_B;
        double var = sh2[0] / (double)PER_B - m*m;
        g_mu[t*NB+bb] = (float)m;
        g_rv[t*NB+bb] = (float)(1.0 / sqrt(var + 1e-5));
    }
}

// ---------------- LN apply: Q,K -> bf16 hi/lo QK concat; V -> fp32 ----------------
__global__ void ln_apply_kernel(const float* __restrict__ kg, const float* __restrict__ kb,
                                const float* __restrict__ qg, const float* __restrict__ qb,
                                const float* __restrict__ vg, const float* __restrict__ vb) {
    int t = blockIdx.z;
    int bb = blockIdx.y;
    const float* base = (t==0 ? g_K : t==1 ? g_Q : g_V) + bb*PER_B;
    const float* g = t==0 ? kg : t==1 ? qg : vg;
    const float* be = t==0 ? kb : t==1 ? qb : vb;
    int off = blockIdx.x*256 + threadIdx.x;
    float mu = g_mu[t*NB+bb], rv = g_rv[t*NB+bb];
    float val = (base[off] - mu) * rv * g[off] + be[off];
    if (t == 2) {
        g_V[bb*PER_B + off] = val;
    } else {
        int d = off & 63;
        int hp = off >> 6;                     // h*NPIX + p
        size_t row = (size_t)bb*HEADS*NPIX + hp;
        int col = d + (t == 0 ? 64 : 0);       // Q in 0..63, K in 64..127
        __nv_bfloat16 h = __float2bfloat16(val);
        g_QKh[row*128 + col] = h;
        g_QKl[row*128 + col] = __float2bfloat16(val - __bfloat162float(h));
    }
}

// ---------------- V transpose + bf16 split: Vt[bh][d][p_pad] ----------------
__global__ void vtrans_kernel() {
    __shared__ float tile[32][65];
    int bhid = blockIdx.x;
    const float* Vb = g_V + (size_t)bhid*NPIX*DH;
    int t = threadIdx.x;
    for (int pt = 0; pt < 20; pt++) {
        int p0 = pt*32;
        for (int i = t; i < 32*64; i += 256) {
            int r = i >> 6, c = i & 63;
            tile[r][c] = (p0 + r < NPIX) ? Vb[(p0 + r)*DH + c] : 0.f;
        }
        __syncthreads();
        for (int i = t; i < 64*32; i += 256) {
            int d = i >> 5, pp = i & 31;
            float v = tile[pp][d];
            __nv_bfloat16 h = __float2bfloat16(v);
            size_t o = ((size_t)bhid*DH + d)*KPAD + p0 + pp;
            g_Vth[o] = h;
            g_Vtl[o] = __float2bfloat16(v - __bfloat162float(h));
        }
        __syncthreads();
    }
}

// ---------------- prep: alin_w transposed bf16 hi/lo ----------------
__global__ void prepw_kernel(const float* __restrict__ alw) {
    int idx = blockIdx.x*256 + threadIdx.x;
    if (idx >= KPAD*KPAD) return;
    int k = idx / KPAD, n = idx % KPAD;
    float v = (k < NPIX && n < NPIX) ? alw[k*NPIX + n] : 0.f;
    __nv_bfloat16 h = __float2bfloat16(v);
    g_Wh[(size_t)n*KPAD + k] = h;
    g_Wl[(size_t)n*KPAD + k] = __float2bfloat16(v - __bfloat162float(h));
}

// ---------------- prep: [qlw;klw] transposed bf16 hi/lo: Wqk[n][128] ----------------
__global__ void prepwqk_kernel(const float* __restrict__ qlw, const float* __restrict__ klw) {
    int idx = blockIdx.x*256 + threadIdx.x;
    if (idx >= KPAD*128) return;
    int n = idx >> 7, k = idx & 127;
    float v = 0.f;
    if (n < NPIX) v = (k < 64) ? qlw[k*NPIX + n] : klw[(k-64)*NPIX + n];
    __nv_bfloat16 h = __float2bfloat16(v);
    g_Wqkh[(size_t)n*128 + k] = h;
    g_Wqkl[(size_t)n*128 + k] = __float2bfloat16(v - __bfloat162float(h));
}

// ---------------- generic tile loader (128 rows x 64 k) ----------------
__device__ __forceinline__ void load_tile16s(__nv_bfloat16* dst,
                                             const __nv_bfloat16* g, size_t row0, int kc,
                                             int tid, int gstride) {
    #pragma unroll
    for (int j = 0; j < 4; j++) {
        int idx = tid + j*GTHR;
        int r = idx >> 3, q = idx & 7;
        *(uint4*)(dst + r*SK + q*8) =
            *(const uint4*)(g + (row0 + r)*(size_t)gstride + kc + q*8);
    }
}

// ---------------- logits GEMM: A = elu(QK @ Wqk^T + bias) -> g_Ah/g_Al ----------------
__global__ __launch_bounds__(GTHR, 2) void logits_gemm_kernel(
    const float* __restrict__ qlb, const float* __restrict__ klb) {
    extern __shared__ __nv_bfloat16 gsm[];
    __nv_bfloat16* sAh = gsm;
    __nv_bfloat16* sAl = gsm + TILE_ELEMS;
    __nv_bfloat16* sWh = gsm + 2*TILE_ELEMS;
    __nv_bfloat16* sWl = gsm + 3*TILE_ELEMS;

    int tid = threadIdx.x;
    int lane = tid & 31;
    int wid = tid >> 5;
    int wm = wid & 3;
    int wn = wid >> 2;
    int n0 = blockIdx.x * 128;
    size_t m0 = (size_t)blockIdx.y * 128;

    float acc[2][8][4];
    #pragma unroll
    for (int mi = 0; mi < 2; mi++)
        #pragma unroll
        for (int ni = 0; ni < 8; ni++)
            #pragma unroll
            for (int k = 0; k < 4; k++) acc[mi][ni][k] = 0.f;

    int lr = lane & 15;
    int lc = (lane >> 4) * 8;

    #pragma unroll
    for (int ch = 0; ch < 2; ch++) {
        int kc = ch * 64;
        load_tile16s(sAh, g_QKh, m0, kc, tid, 128);
        load_tile16s(sAl, g_QKl, m0, kc, tid, 128);
        load_tile16s(sWh, g_Wqkh, n0, kc, tid, 128);
        load_tile16s(sWl, g_Wqkl, n0, kc, tid, 128);
        __syncthreads();
        #pragma unroll
        for (int ks = 0; ks < 4; ks++) {
            int col = ks*16 + lc;
            uint32_t ah[2][4], al[2][4];
            #pragma unroll
            for (int mi = 0; mi < 2; mi++) {
                int row = wm*32 + mi*16 + lr;
                ldsm4(ah[mi], (uint32_t)__cvta_generic_to_shared(sAh + row*SK + col));
                ldsm4(al[mi], (uint32_t)__cvta_generic_to_shared(sAl + row*SK + col));
            }
            #pragma unroll
            for (int nb = 0; nb < 4; nb++) {
                int nrow = wn*64 + nb*16 + lr;
                uint32_t wbh[4], wbl[4];
                ldsm4(wbh, (uint32_t)__cvta_generic_to_shared(sWh + nrow*SK + col));
                ldsm4(wbl, (uint32_t)__cvta_generic_to_shared(sWl + nrow*SK + col));
                #pragma unroll
                for (int mi = 0; mi < 2; mi++) {
                    mma16816(acc[mi][2*nb],   ah[mi], wbh[0], wbh[2]);
                    mma16816(acc[mi][2*nb+1], ah[mi], wbh[1], wbh[3]);
                    mma16816(acc[mi][2*nb],   ah[mi], wbl[0], wbl[2]);
                    mma16816(acc[mi][2*nb+1], ah[mi], wbl[1], wbl[3]);
                    mma16816(acc[mi][2*nb],   al[mi], wbh[0], wbh[2]);
                    mma16816(acc[mi][2*nb+1], al[mi], wbh[1], wbh[3]);
                }
            }
        }
        __syncthreads();
    }

    // epilogue: elu(acc + bias) -> bf16 hi/lo (pad cols auto-zero via zeroed W, bias guard)
    #pragma unroll
    for (int mi = 0; mi < 2; mi++) {
        #pragma unroll
        for (int ni = 0; ni < 8; ni++) {
            int n = n0 + wn*64 + ni*8 + (lane & 3)*2;
            float b0 = (n < NPIX)   ? qlb[n] + klb[n]     : 0.f;
            float b1 = (n+1 < NPIX) ? qlb[n+1] + klb[n+1] : 0.f;
            #pragma unroll
            for (int half = 0; half < 2; half++) {
                size_t m = m0 + wm*32 + mi*16 + (lane >> 2) + half*8;
                float a0 = eluf(acc[mi][ni][2*half]   + b0);
                float a1 = eluf(acc[mi][ni][2*half+1] + b1);
                __nv_bfloat16 h0 = __float2bfloat16(a0);
                __nv_bfloat16 h1 = __float2bfloat16(a1);
                __nv_bfloat162 ph; ph.x = h0; ph.y = h1;
                __nv_bfloat162 pl;
                pl.x = __float2bfloat16(a0 - __bfloat162float(h0));
                pl.y = __float2bfloat16(a1 - __bfloat162float(h1));
                *(__nv_bfloat162*)(g_Ah + m*KPAD + n) = ph;
                *(__nv_bfloat162*)(g_Al + m*KPAD + n) = pl;
            }
        }
    }
}

// ---------------- main GEMM: S = A @ W^T + alb ----------------
__global__ __launch_bounds__(GTHR, 2) void gemm_kernel(const float* __restrict__ alb) {
    extern __shared__ __nv_bfloat16 gsm[];
    __nv_bfloat16* sAh = gsm;
    __nv_bfloat16* sAl = gsm + TILE_ELEMS;
    __nv_bfloat16* sWh = gsm + 2*TILE_ELEMS;
    __nv_bfloat16* sWl = gsm + 3*TILE_ELEMS;

    int tid = threadIdx.x;
    int lane = tid & 31;
    int wid = tid >> 5;
    int wm = wid & 3;
    int wn = wid >> 2;
    int n0 = blockIdx.x * 128;
    size_t m0 = (size_t)blockIdx.y * 128;

    float acc[2][8][4];
    #pragma unroll
    for (int mi = 0; mi < 2; mi++)
        #pragma unroll
        for (int ni = 0; ni < 8; ni++)
            #pragma unroll
            for (int k = 0; k < 4; k++) acc[mi][ni][k] = 0.f;

    int lr = lane & 15;
    int lc = (lane >> 4) * 8;

    for (int ch = 0; ch < 10; ch++) {
        int kc = ch * 64;
        load_tile16s(sAh, g_Ah, m0, kc, tid, KPAD);
        load_tile16s(sAl, g_Al, m0, kc, tid, KPAD);
        load_tile16s(sWh, g_Wh, n0, kc, tid, KPAD);
        load_tile16s(sWl, g_Wl, n0, kc, tid, KPAD);
        __syncthreads();
        #pragma unroll
        for (int ks = 0; ks < 4; ks++) {
            int col = ks*16 + lc;
            uint32_t ah[2][4], al[2][4];
            #pragma unroll
            for (int mi = 0; mi < 2; mi++) {
                int row = wm*32 + mi*16 + lr;
                ldsm4(ah[mi], (uint32_t)__cvta_generic_to_shared(sAh + row*SK + col));
                ldsm4(al[mi], (uint32_t)__cvta_generic_to_shared(sAl + row*SK + col));
            }
            #pragma unroll
            for (int nb = 0; nb < 4; nb++) {
                int nrow = wn*64 + nb*16 + lr;
                uint32_t wbh[4], wbl[4];
                ldsm4(wbh, (uint32_t)__cvta_generic_to_shared(sWh + nrow*SK + col));
                ldsm4(wbl, (uint32_t)__cvta_generic_to_shared(sWl + nrow*SK + col));
                #pragma unroll
                for (int mi = 0; mi < 2; mi++) {
                    mma16816(acc[mi][2*nb],   ah[mi], wbh[0], wbh[2]);
                    mma16816(acc[mi][2*nb+1], ah[mi], wbh[1], wbh[3]);
                    mma16816(acc[mi][2*nb],   ah[mi], wbl[0], wbl[2]);
                    mma16816(acc[mi][2*nb+1], ah[mi], wbl[1], wbl[3]);
                    mma16816(acc[mi][2*nb],   al[mi], wbh[0], wbh[2]);
                    mma16816(acc[mi][2*nb+1], al[mi], wbh[1], wbh[3]);
                }
            }
        }
        __syncthreads();
    }

    #pragma unroll
    for (int mi = 0; mi < 2; mi++) {
        #pragma unroll
        for (int ni = 0; ni < 8; ni++) {
            int n = n0 + wn*64 + ni*8 + (lane & 3)*2;
            #pragma unroll
            for (int half = 0; half < 2; half++) {
                size_t m = m0 + wm*32 + mi*16 + (lane >> 2) + half*8;
                if (n + 1 < NPIX) {
                    float2 o;
                    o.x = acc[mi][ni][2*half]   + alb[n];
                    o.y = acc[mi][ni][2*half+1] + alb[n+1];
                    *(float2*)(g_S + m*NPIX + n) = o;
                } else if (n < NPIX) {
                    g_S[m*NPIX + n] = acc[mi][ni][2*half] + alb[n];
                }
            }
        }
    }
}

// ---------------- softmax: g_S -> P bf16 hi/lo into g_Ah/g_Al ----------------
__global__ __launch_bounds__(256) void softmax_kernel() {
    size_t row = (size_t)blockIdx.x*8 + (threadIdx.x >> 5);
    int lane = threadIdx.x & 31;
    const float* S = g_S + row*NPIX;
    __nv_bfloat16* Ph = g_Ah + row*KPAD;
    __nv_bfloat16* Pl = g_Al + row*KPAD;
    float v[19];
    float m = -1e30f;
    #pragma unroll
    for (int i = 0; i < 19; i++) {
        int j = lane + 32*i;
        v[i] = (j < NPIX) ? S[j] : -1e30f;
        m = fmaxf(m, v[i]);
    }
    #pragma unroll
    for (int o = 16; o; o >>= 1) m = fmaxf(m, __shfl_xor_sync(0xffffffffu, m, o));
    float s = 0.f;
    #pragma unroll
    for (int i = 0; i < 19; i++) {
        v[i] = __expf(v[i] - m);
        s += v[i];
    }
    #pragma unroll
    for (int o = 16; o; o >>= 1) s += __shfl_xor_sync(0xffffffffu, s, o);
    float inv = 1.f / s;
    #pragma unroll
    for (int i = 0; i < 19; i++) {
        int j = lane + 32*i;
        if (j < NPIX) {
            float pv = v[i]*inv;
            __nv_bfloat16 h = __float2bfloat16(pv);
            Ph[j] = h;
            Pl[j] = __float2bfloat16(pv - __bfloat162float(h));
        } else {
            Ph[j] = __float2bfloat16(0.f);
            Pl[j] = __float2bfloat16(0.f);
        }
    }
    {
        int j = 608 + lane;
        Ph[j] = __float2bfloat16(0.f);
        Pl[j] = __float2bfloat16(0.f);
    }
}

// ---------------- E GEMM: E = P @ Vt^T per bh ----------------
__global__ __launch_bounds__(GTHR, 2) void e_gemm_kernel() {
    extern __shared__ __nv_bfloat16 esm[];
    __nv_bfloat16* sPh = esm;                    // 128 x SK
    __nv_bfloat16* sPl = esm + 128*SK;
    __nv_bfloat16* sVh = esm + 2*128*SK;         // 64 x SK
    __nv_bfloat16* sVl = esm + 2*128*SK + 64*SK;

    int tid = threadIdx.x;
    int lane = tid & 31;
    int wid = tid >> 5;                          // 0..7: 16 rows each
    int mt = blockIdx.x;                         // 0..4
    int bhid = blockIdx.y;                       // 0..255
    int p00 = mt * 128;
    int bb = bhid >> 2, h = bhid & 3;

    float acc[8][4];
    #pragma unroll
    for (int ni = 0; ni < 8; ni++)
        #pragma unroll
        for (int k = 0; k < 4; k++) acc[ni][k] = 0.f;

    int lr = lane & 15;
    int lc = (lane >> 4) * 8;

    for (int ch = 0; ch < 10; ch++) {
        int kc = ch * 64;
        // P tile: 128 rows (clamped to NPIX-1)
        #pragma unroll
        for (int j = 0; j < 4; j++) {
            int idx = tid + j*GTHR;
            int r = idx >> 3, q = idx & 7;
            int p = p00 + r; if (p > NPIX-1) p = NPIX-1;
            size_t row = (size_t)bhid*NPIX + p;
            *(uint4*)(sPh + r*SK + q*8) = *(const uint4*)(g_Ah + row*KPAD + kc + q*8);
            *(uint4*)(sPl + r*SK + q*8) = *(const uint4*)(g_Al + row*KPAD + kc + q*8);
        }
        // V tile: 64 rows
        #pragma unroll
        for (int j = 0; j < 2; j++) {
            int idx = tid + j*GTHR;
            int r = idx >> 3, q = idx & 7;
            size_t row = (size_t)bhid*DH + r;
            *(uint4*)(sVh + r*SK + q*8) = *(const uint4*)(g_Vth + row*KPAD + kc + q*8);
            *(uint4*)(sVl + r*SK + q*8) = *(const uint4*)(g_Vtl + row*KPAD + kc + q*8);
        }
        __syncthreads();
        #pragma unroll
        for (int ks = 0; ks < 4; ks++) {
            int col = ks*16 + lc;
            uint32_t ph[4], pl[4];
            int row = wid*16 + lr;
            ldsm4(ph, (uint32_t)__cvta_generic_to_shared(sPh + row*SK + col));
            ldsm4(pl, (uint32_t)__cvta_generic_to_shared(sPl + row*SK + col));
            #pragma unroll
            for (int nb = 0; nb < 4; nb++) {
                int nrow = nb*16 + lr;
                uint32_t vbh[4], vbl[4];
                ldsm4(vbh, (uint32_t)__cvta_generic_to_shared(sVh + nrow*SK + col));
                ldsm4(vbl, (uint32_t)__cvta_generic_to_shared(sVl + nrow*SK + col));
                mma16816(acc[2*nb],   ph, vbh[0], vbh[2]);
                mma16816(acc[2*nb+1], ph, vbh[1], vbh[3]);
                mma16816(acc[2*nb],   ph, vbl[0], vbl[2]);
                mma16816(acc[2*nb+1], ph, vbl[1], vbl[3]);
                mma16816(acc[2*nb],   pl, vbh[0], vbh[2]);
                mma16816(acc[2*nb+1], pl, vbh[1], vbh[3]);
            }
        }
        __syncthreads();
    }

    // epilogue: E[(bb,p), h*64+d] fp32
    #pragma unroll
    for (int ni = 0; ni < 8; ni++) {
        int d = ni*8 + (lane & 3)*2;
        #pragma unroll
        for (int half = 0; half < 2; half++) {
            int p = p00 + wid*16 + (lane >> 2) + half*8;
            if (p < NPIX) {
                float2 o; o.x = acc[ni][2*half]; o.y = acc[ni][2*half+1];
                *(float2*)(g_E + ((size_t)bb*NPIX + p)*256 + h*DH + d) = o;
            }
        }
    }
}

// ---------------- lin1 + relu ----------------
__global__ void lin1_kernel(const float* __restrict__ w, const float* __restrict__ b) {
    int idx = blockIdx.x * blockDim.x + threadIdx.x;
    if (idx >= NB*NPIX*DH) return;
    int d = idx & 63;
    int bp = idx >> 6;
    const float* e = g_E + (size_t)bp*256;
    float acc = b[d];
    #pragma unroll 8
    for (int c = 0; c < 256; c++) acc += e[c] * w[c*DH + d];
    g_F[idx] = fmaxf(acc, 0.f);
}

// ---------------- LN2 stats ----------------
__global__ void ln2_stats_kernel() {
    int bb = blockIdx.x;
    const float* base = g_F + bb*NPIX*DH;
    const int n = NPIX*DH;
    float s = 0.f, ss = 0.f;
    for (int i = threadIdx.x; i < n; i += blockDim.x) {
        float v = base[i]; s += v; ss += v*v;
    }
    __shared__ double sh[256], sh2[256];
    sh[threadIdx.x] = (double)s; sh2[threadIdx.x] = (double)ss; __syncthreads();
    for (int o = 128; o; o >>= 1) {
        if (threadIdx.x < o) { sh[threadIdx.x] += sh[threadIdx.x+o]; sh2[threadIdx.x] += sh2[threadIdx.x+o]; }
        __syncthreads();
    }
    if (threadIdx.x == 0) {
        double m = sh[0] / (double)n;
        double var = sh2[0] / (double)n - m*m;
        g_mu2[bb] = (float)m;
        g_rv2[bb] = (float)(1.0 / sqrt(var + 1e-5));
    }
}

// ---------------- LN2 apply + max ----------------
__global__ void ln2max_kernel() {
    int bb = blockIdx.x;
    int d = threadIdx.x & 63, pc = threadIdx.x >> 6;
    float mu = g_mu2[bb], rv = g_rv2[bb];
    float m = -1e30f;
    for (int p = pc; p < NPIX; p += 4) {
        float v = (g_F[(bb*NPIX + p)*DH + d] - mu) * rv;
        m = fmaxf(m, v);
    }
    __shared__ float sh[256];
    sh[threadIdx.x] = m; __syncthreads();
    if (pc == 0) {
        m = fmaxf(fmaxf(sh[d], sh[64+d]), fmaxf(sh[128+d], sh[192+d]));
        g_M[bb*DH + d] = m;
    }
}

// ---------------- final lin2 + elu ----------------
__global__ void final_kernel(const float* __restrict__ w, const float* __restrict__ b,
                             float* __restrict__ out) {
    int idx = blockIdx.x * blockDim.x + threadIdx.x;
    if (idx >= NB*10) return;
    int bb = idx / 10, j = idx % 10;
    float acc = b[j];
    #pragma unroll
    for (int d = 0; d < DH; d++) acc += g_M[bb*DH + d] * w[d*10 + j];
    out[idx] = eluf(acc);
}

extern "C" void kernel_launch(void* const* d_in, const int* in_sizes, int n_in,
                              void* d_out, int out_size) {
    const float* x       = (const float*)d_in[0];
    const float* conv1_w = (const float*)d_in[1];
    const float* conv1_b = (const float*)d_in[2];
    const float* conv2_w = (const float*)d_in[3];
    const float* conv2_b = (const float*)d_in[4];
    const float* kp_w    = (const float*)d_in[5];
    const float* kp_b    = (const float*)d_in[6];
    const float* qp_w    = (const float*)d_in[7];
    const float* qp_b    = (const float*)d_in[8];
    const float* vp_w    = (const float*)d_in[9];
    const float* vp_b    = (const float*)d_in[10];
    const float* klin_w  = (const float*)d_in[11];
    const float* klin_b  = (const float*)d_in[12];
    const float* qlin_w  = (const float*)d_in[13];
    const float* qlin_b  = (const float*)d_in[14];
    const float* alin_w  = (const float*)d_in[15];
    const float* alin_b  = (const float*)d_in[16];
    const float* knorm_g = (const float*)d_in[17];
    const float* knorm_b = (const float*)d_in[18];
    const float* qnorm_g = (const float*)d_in[19];
    const float* qnorm_b = (const float*)d_in[20];
    const float* vnorm_g = (const float*)d_in[21];
    const float* vnorm_b = (const float*)d_in[22];
    const float* lin1_w  = (const float*)d_in[23];
    const float* lin1_b  = (const float*)d_in[24];
    const float* lin2_w  = (const float*)d_in[25];
    const float* lin2_b  = (const float*)d_in[26];
    float* out = (float*)d_out;

    cudaFuncSetAttribute(logits_gemm_kernel, cudaFuncAttributeMaxDynamicSharedMemorySize, GEMM_SMEM);
    cudaFuncSetAttribute(gemm_kernel,        cudaFuncAttributeMaxDynamicSharedMemorySize, GEMM_SMEM);
    cudaFuncSetAttribute(e_gemm_kernel,      cudaFuncAttributeMaxDynamicSharedMemorySize, EGEMM_SMEM);

    conv1_kernel<<<(NB*16*150*5 + 255)/256, 256>>>(x, conv1_w, conv1_b);
    conv2_feats_kernel<<<(NB*NPIX*34 + 255)/256, 256>>>(conv2_w, conv2_b);
    {
        dim3 g((NB*NPIX*256 + 255)/256, 3);
        proj_kernel<<<g, 256>>>(kp_w, kp_b, qp_w, qp_b, vp_w, vp_b);
    }
    {
        dim3 g(NB, 3);
        ln_stats_kernel<<<g, 256>>>();
    }
    {
        dim3 g(PER_B/256, NB, 3);
        ln_apply_kernel<<<g, 256>>>(knorm_g, knorm_b, qnorm_g, qnorm_b, vnorm_g, vnorm_b);
    }
    vtrans_kernel<<<NB*HEADS, 256>>>();
    prepw_kernel<<<(KPAD*KPAD + 255)/256, 256>>>(alin_w);
    prepwqk_kernel<<<(KPAD*128 + 255)/256, 256>>>(qlin_w, klin_w);
    {
        dim3 g(KPAD/128, MROWS/128);               // (5, 1192)
        logits_gemm_kernel<<<g, GTHR, GEMM_SMEM>>>(qlin_b, klin_b);
    }
    {
        dim3 g(KPAD/128, MROWS/128);               // (5, 1192)
        gemm_kernel<<<g, GTHR, GEMM_SMEM>>>(alin_b);
    }
    softmax_kernel<<<MROWS/8, 256>>>();
    {
        dim3 g(5, NB*HEADS);                       // (5, 256)
        e_gemm_kernel<<<g, GTHR, EGEMM_SMEM>>>();
    }
    lin1_kernel<<<(NB*NPIX*DH + 255)/256, 256>>>(lin1_w, lin1_b);
    ln2_stats_kernel<<<NB, 256>>>();
    ln2max_kernel<<<NB, 256>>>();
    final_kernel<<<3, 256>>>(lin2_w, lin2_b, out);
}

// round 8
// speedup vs baseline: 2.5393x; 1.0156x over previous
#include <cuda_runtime.h>
#include <cuda_bf16.h>
#include <math.h>
#include <stdint.h>

#define NB 64
#define NPIX 596
#define HEADS 4
#define DH 64
#define PER_B (HEADS*NPIX*DH)   // 152576
#define MROWS (NB*HEADS*NPIX)   // 152576
#define KPAD 640

// ---- gemm common ----
#define GTHR 256
#define SK 72
#define TILE_ELEMS (128*SK)
#define GEMM_SMEM (4*TILE_ELEMS*2)              // logits gemm (unpipelined): 73728
// pipelined gemm: k-chunk 32, double buffered
#define KC 32
#define NCH (KPAD/KC)                           // 20
#define SK2 40
#define BUF_T (128*SK2)                         // elems per 128-row tile
#define VBUF_T (64*SK2)
#define GEMM2_BUF (4*BUF_T)
#define GEMM2_SMEM (2*GEMM2_BUF*2)              // 81920 bytes
#define EBUF (2*BUF_T + 2*VBUF_T)
#define EGEMM2_SMEM (2*EBUF*2)                  // 61440 bytes

// ---------------- scratch ----------------
__device__ float g_conv1[NB*16*150*5];
__device__ float g_feats[NB*NPIX*34];
__device__ float g_K[NB*HEADS*NPIX*DH];
__device__ float g_Q[NB*HEADS*NPIX*DH];
__device__ float g_V[NB*HEADS*NPIX*DH];
__device__ float g_mu[3*NB], g_rv[3*NB];
__device__ __nv_bfloat16 g_QKh[(size_t)MROWS*128];
__device__ __nv_bfloat16 g_QKl[(size_t)MROWS*128];
__device__ __nv_bfloat16 g_Wqkh[(size_t)KPAD*128];
__device__ __nv_bfloat16 g_Wqkl[(size_t)KPAD*128];
__device__ __nv_bfloat16 g_Ah[(size_t)MROWS*KPAD];   // logits A, then P after softmax
__device__ __nv_bfloat16 g_Al[(size_t)MROWS*KPAD];
__device__ __nv_bfloat16 g_Wh[(size_t)KPAD*KPAD];
__device__ __nv_bfloat16 g_Wl[(size_t)KPAD*KPAD];
__device__ __nv_bfloat16 g_Vth[(size_t)NB*HEADS*DH*KPAD];
__device__ __nv_bfloat16 g_Vtl[(size_t)NB*HEADS*DH*KPAD];
__device__ float g_S[(size_t)MROWS*NPIX];
__device__ float g_E[(size_t)NB*NPIX*256];
__device__ float g_F[NB*NPIX*DH];
__device__ float g_mu2[NB], g_rv2[NB];
__device__ float g_M[NB*DH];

__device__ __forceinline__ float eluf(float x) {
    return x > 0.f ? x : (__expf(x) - 1.f);
}

// ---- mma.sync helpers ----
__device__ __forceinline__ void ldsm4(uint32_t* r, uint32_t addr) {
    asm volatile("ldmatrix.sync.aligned.m8n8.x4.shared.b16 {%0,%1,%2,%3}, [%4];"
        : "=r"(r[0]), "=r"(r[1]), "=r"(r[2]), "=r"(r[3]) : "r"(addr));
}
__device__ __forceinline__ void mma16816(float* c, const uint32_t* a,
                                         uint32_t b0, uint32_t b1) {
    asm volatile(
        "mma.sync.aligned.m16n8k16.row.col.f32.bf16.bf16.f32 "
        "{%0,%1,%2,%3}, {%4,%5,%6,%7}, {%8,%9}, {%0,%1,%2,%3};"
        : "+f"(c[0]), "+f"(c[1]), "+f"(c[2]), "+f"(c[3])
        : "r"(a[0]), "r"(a[1]), "r"(a[2]), "r"(a[3]), "r"(b0), "r"(b1));
}
// ---- cp.async helpers ----
__device__ __forceinline__ void cp16(void* smem, const void* gmem) {
    uint32_t s = (uint32_t)__cvta_generic_to_shared(smem);
    asm volatile("cp.async.cg.shared.global [%0], [%1], 16;" :: "r"(s), "l"(gmem));
}
#define CP_COMMIT() asm volatile("cp.async.commit_group;" ::: "memory")
#define CP_WAIT1()  asm volatile("cp.async.wait_group 1;" ::: "memory")
#define CP_WAIT0()  asm volatile("cp.async.wait_group 0;" ::: "memory")

// ---------------- conv1 + relu ----------------
__global__ void conv1_kernel(const float* __restrict__ x,
                             const float* __restrict__ w,
                             const float* __restrict__ b) {
    int idx = blockIdx.x * blockDim.x + threadIdx.x;
    if (idx >= NB*16*150*5) return;
    int ow = idx % 5;
    int oh = (idx / 5) % 150;
    int co = (idx / (5*150)) % 16;
    int bb = idx / (5*150*16);
    float acc = b[co];
    #pragma unroll
    for (int ci = 0; ci < 4; ci++)
        #pragma unroll
        for (int kh = 0; kh < 2; kh++)
            #pragma unroll
            for (int kw = 0; kw < 2; kw++)
                acc += x[((bb*4+ci)*151 + oh+kh)*6 + ow+kw] *
                       w[((co*4+ci)*2 + kh)*2 + kw];
    g_conv1[idx] = fmaxf(acc, 0.f);
}

// ---------------- conv2 + relu + coords -> feats ----------------
__global__ void conv2_feats_kernel(const float* __restrict__ w,
                                   const float* __restrict__ b) {
    int idx = blockIdx.x * blockDim.x + threadIdx.x;
    if (idx >= NB*NPIX*34) return;
    int c = idx % 34;
    int p = (idx / 34) % NPIX;
    int bb = idx / (34*NPIX);
    int oh = p / 4, ow = p % 4;
    float val;
    if (c < 32) {
        float acc = b[c];
        #pragma unroll 4
        for (int ci = 0; ci < 16; ci++)
            #pragma unroll
            for (int kh = 0; kh < 2; kh++)
                #pragma unroll
                for (int kw = 0; kw < 2; kw++)
                    acc += g_conv1[((bb*16+ci)*150 + oh+kh)*5 + ow+kw] *
                           w[((c*16+ci)*2 + kh)*2 + kw];
        val = fmaxf(acc, 0.f);
    } else if (c == 32) {
        val = (float)ow / 4.f;
    } else {
        val = (float)oh / 149.f;
    }
    g_feats[idx] = val;
}

// ---------------- K/Q/V projections ----------------
__global__ void proj_kernel(const float* __restrict__ kw, const float* __restrict__ kb,
                            const float* __restrict__ qw, const float* __restrict__ qb,
                            const float* __restrict__ vw, const float* __restrict__ vb) {
    int t = blockIdx.y;
    const float* W = t==0 ? kw : t==1 ? qw : vw;
    const float* B = t==0 ? kb : t==1 ? qb : vb;
    float* O = t==0 ? g_K : t==1 ? g_Q : g_V;
    int idx = blockIdx.x * blockDim.x + threadIdx.x;
    if (idx >= NB*NPIX*256) return;
    int hd = idx & 255;
    int bp = idx >> 8;
    int p = bp % NPIX, bb = bp / NPIX;
    const float* f = g_feats + bp*34;
    float acc = B[hd];
    #pragma unroll
    for (int c = 0; c < 34; c++) acc += f[c] * W[c*256 + hd];
    int h = hd >> 6, d = hd & 63;
    O[((bb*HEADS + h)*NPIX + p)*DH + d] = acc;
}

// ---------------- LN stats (512 thr, float4) ----------------
__global__ __launch_bounds__(512) void ln_stats_kernel() {
    int bb = blockIdx.x, t = blockIdx.y;
    const float4* base = (const float4*)((t==0 ? g_K : t==1 ? g_Q : g_V) + bb*PER_B);
    const int n4 = PER_B/4;
    float s = 0.f, ss = 0.f;
    for (int i = threadIdx.x; i < n4; i += 512) {
        float4 v = base[i];
        s  += v.x + v.y + v.z + v.w;
        ss += v.x*v.x + v.y*v.y + v.z*v.z + v.w*v.w;
    }
    __shared__ double sh[512], sh2[512];
    sh[threadIdx.x] = (double)s; sh2[threadIdx.x] = (double)ss; __syncthreads();
    for (int o = 256; o; o >>= 1) {
        if (threadIdx.x < o) { sh[threadIdx.x] += sh[threadIdx.x+o]; sh2[threadIdx.x] += sh2[threadIdx.x+o]; }
        __syncthreads();
    }
    if (threadIdx.x == 0) {
        double m = sh[0] / (double)PER_B;
        double var = sh2[0] / (double)PER_B - m*m;
        g_mu[t*NB+bb] = (float)m;
        g_rv[t*NB+bb] = (float)(1.0 / sqrt(var + 1e-5));
    }
}

// ---------------- LN apply (float4/thread): Q,K -> bf16 hi/lo QK; V -> fp32 ----------------
__global__ void ln_apply_kernel(const float* __restrict__ kg, const float* __restrict__ kb,
                                const float* __restrict__ qg, const float* __restrict__ qb,
                                const float* __restrict__ vg, const float* __restrict__ vb) {
    int t = blockIdx.z;
    int bb = blockIdx.y;
    const float* base = (t==0 ? g_K : t==1 ? g_Q : g_V) + bb*PER_B;
    const float* g = t==0 ? kg : t==1 ? qg : vg;
    const float* be = t==0 ? kb : t==1 ? qb : vb;
    int off = (blockIdx.x*256 + threadIdx.x)*4;
    float mu = g_mu[t*NB+bb], rv = g_rv[t*NB+bb];
    float4 v  = *(const float4*)(base + off);
    float4 gg = *(const float4*)(g + off);
    float4 bv = *(const float4*)(be + off);
    float4 r;
    r.x = (v.x - mu)*rv*gg.x + bv.x;
    r.y = (v.y - mu)*rv*gg.y + bv.y;
    r.z = (v.z - mu)*rv*gg.z + bv.z;
    r.w = (v.w - mu)*rv*gg.w + bv.w;
    if (t == 2) {
        *(float4*)(g_V + bb*PER_B + off) = r;
    } else {
        int d = off & 63;
        int hp = off >> 6;
        size_t row = (size_t)bb*HEADS*NPIX + hp;
        int col = d + (t == 0 ? 64 : 0);
        __nv_bfloat162 h0, h1, l0, l1;
        h0.x = __float2bfloat16(r.x); h0.y = __float2bfloat16(r.y);
        h1.x = __float2bfloat16(r.z); h1.y = __float2bfloat16(r.w);
        l0.x = __float2bfloat16(r.x - __bfloat162float(h0.x));
        l0.y = __float2bfloat16(r.y - __bfloat162float(h0.y));
        l1.x = __float2bfloat16(r.z - __bfloat162float(h1.x));
        l1.y = __float2bfloat16(r.w - __bfloat162float(h1.y));
        *(__nv_bfloat162*)(g_QKh + row*128 + col)     = h0;
        *(__nv_bfloat162*)(g_QKh + row*128 + col + 2) = h1;
        *(__nv_bfloat162*)(g_QKl + row*128 + col)     = l0;
        *(__nv_bfloat162*)(g_QKl + row*128 + col + 2) = l1;
    }
}

// ---------------- V transpose + bf16 split ----------------
__global__ void vtrans_kernel() {
    __shared__ float tile[32][65];
    int bhid = blockIdx.x;
    const float* Vb = g_V + (size_t)bhid*NPIX*DH;
    int t = threadIdx.x;
    for (int pt = 0; pt < 20; pt++) {
        int p0 = pt*32;
        for (int i = t; i < 32*64; i += 256) {
            int r = i >> 6, c = i & 63;
            tile[r][c] = (p0 + r < NPIX) ? Vb[(p0 + r)*DH + c] : 0.f;
        }
        __syncthreads();
        for (int i = t; i < 64*32; i += 256) {
            int d = i >> 5, pp = i & 31;
            float v = tile[pp][d];
            __nv_bfloat16 h = __float2bfloat16(v);
            size_t o = ((size_t)bhid*DH + d)*KPAD + p0 + pp;
            g_Vth[o] = h;
            g_Vtl[o] = __float2bfloat16(v - __bfloat162float(h));
        }
        __syncthreads();
    }
}

// ---------------- prep: alin_w transposed bf16 hi/lo ----------------
__global__ void prepw_kernel(const float* __restrict__ alw) {
    int idx = blockIdx.x*256 + threadIdx.x;
    if (idx >= KPAD*KPAD) return;
    int k = idx / KPAD, n = idx % KPAD;
    float v = (k < NPIX && n < NPIX) ? alw[k*NPIX + n] : 0.f;
    __nv_bfloat16 h = __float2bfloat16(v);
    g_Wh[(size_t)n*KPAD + k] = h;
    g_Wl[(size_t)n*KPAD + k] = __float2bfloat16(v - __bfloat162float(h));
}

// ---------------- prep: [qlw;klw] transposed bf16 hi/lo ----------------
__global__ void prepwqk_kernel(const float* __restrict__ qlw, const float* __restrict__ klw) {
    int idx = blockIdx.x*256 + threadIdx.x;
    if (idx >= KPAD*128) return;
    int n = idx >> 7, k = idx & 127;
    float v = 0.f;
    if (n < NPIX) v = (k < 64) ? qlw[k*NPIX + n] : klw[(k-64)*NPIX + n];
    __nv_bfloat16 h = __float2bfloat16(v);
    g_Wqkh[(size_t)n*128 + k] = h;
    g_Wqkl[(size_t)n*128 + k] = __float2bfloat16(v - __bfloat162float(h));
}

// ---------------- generic sync tile loader (logits gemm) ----------------
__device__ __forceinline__ void load_tile16s(__nv_bfloat16* dst,
                                             const __nv_bfloat16* g, size_t row0, int kc,
                                             int tid, int gstride) {
    #pragma unroll
    for (int j = 0; j < 4; j++) {
        int idx = tid + j*GTHR;
        int r = idx >> 3, q = idx & 7;
        *(uint4*)(dst + r*SK + q*8) =
            *(const uint4*)(g + (row0 + r)*(size_t)gstride + kc + q*8);
    }
}

// ---------------- logits GEMM: A = elu(QK @ Wqk^T + bias) ----------------
__global__ __launch_bounds__(GTHR, 2) void logits_gemm_kernel(
    const float* __restrict__ qlb, const float* __restrict__ klb) {
    extern __shared__ __nv_bfloat16 gsm[];
    __nv_bfloat16* sAh = gsm;
    __nv_bfloat16* sAl = gsm + TILE_ELEMS;
    __nv_bfloat16* sWh = gsm + 2*TILE_ELEMS;
    __nv_bfloat16* sWl = gsm + 3*TILE_ELEMS;

    int tid = threadIdx.x;
    int lane = tid & 31;
    int wid = tid >> 5;
    int wm = wid & 3;
    int wn = wid >> 2;
    int n0 = blockIdx.x * 128;
    size_t m0 = (size_t)blockIdx.y * 128;

    float acc[2][8][4];
    #pragma unroll
    for (int mi = 0; mi < 2; mi++)
        #pragma unroll
        for (int ni = 0; ni < 8; ni++)
            #pragma unroll
            for (int k = 0; k < 4; k++) acc[mi][ni][k] = 0.f;

    int lr = lane & 15;
    int lc = (lane >> 4) * 8;

    #pragma unroll
    for (int ch = 0; ch < 2; ch++) {
        int kc = ch * 64;
        load_tile16s(sAh, g_QKh, m0, kc, tid, 128);
        load_tile16s(sAl, g_QKl, m0, kc, tid, 128);
        load_tile16s(sWh, g_Wqkh, n0, kc, tid, 128);
        load_tile16s(sWl, g_Wqkl, n0, kc, tid, 128);
        __syncthreads();
        #pragma unroll
        for (int ks = 0; ks < 4; ks++) {
            int col = ks*16 + lc;
            uint32_t ah[2][4], al[2][4];
            #pragma unroll
            for (int mi = 0; mi < 2; mi++) {
                int row = wm*32 + mi*16 + lr;
                ldsm4(ah[mi], (uint32_t)__cvta_generic_to_shared(sAh + row*SK + col));
                ldsm4(al[mi], (uint32_t)__cvta_generic_to_shared(sAl + row*SK + col));
            }
            #pragma unroll
            for (int nb = 0; nb < 4; nb++) {
                int nrow = wn*64 + nb*16 + lr;
                uint32_t wbh[4], wbl[4];
                ldsm4(wbh, (uint32_t)__cvta_generic_to_shared(sWh + nrow*SK + col));
                ldsm4(wbl, (uint32_t)__cvta_generic_to_shared(sWl + nrow*SK + col));
                #pragma unroll
                for (int mi = 0; mi < 2; mi++) {
                    mma16816(acc[mi][2*nb],   ah[mi], wbh[0], wbh[2]);
                    mma16816(acc[mi][2*nb+1], ah[mi], wbh[1], wbh[3]);
                    mma16816(acc[mi][2*nb],   ah[mi], wbl[0], wbl[2]);
                    mma16816(acc[mi][2*nb+1], ah[mi], wbl[1], wbl[3]);
                    mma16816(acc[mi][2*nb],   al[mi], wbh[0], wbh[2]);
                    mma16816(acc[mi][2*nb+1], al[mi], wbh[1], wbh[3]);
                }
            }
        }
        __syncthreads();
    }

    #pragma unroll
    for (int mi = 0; mi < 2; mi++) {
        #pragma unroll
        for (int ni = 0; ni < 8; ni++) {
            int n = n0 + wn*64 + ni*8 + (lane & 3)*2;
            float b0 = (n < NPIX)   ? qlb[n] + klb[n]     : 0.f;
            float b1 = (n+1 < NPIX) ? qlb[n+1] + klb[n+1] : 0.f;
            #pragma unroll
            for (int half = 0; half < 2; half++) {
                size_t m = m0 + wm*32 + mi*16 + (lane >> 2) + half*8;
                float a0 = eluf(acc[mi][ni][2*half]   + b0);
                float a1 = eluf(acc[mi][ni][2*half+1] + b1);
                __nv_bfloat16 h0 = __float2bfloat16(a0);
                __nv_bfloat16 h1 = __float2bfloat16(a1);
                __nv_bfloat162 ph; ph.x = h0; ph.y = h1;
                __nv_bfloat162 pl;
                pl.x = __float2bfloat16(a0 - __bfloat162float(h0));
                pl.y = __float2bfloat16(a1 - __bfloat162float(h1));
                *(__nv_bfloat162*)(g_Ah + m*KPAD + n) = ph;
                *(__nv_bfloat162*)(g_Al + m*KPAD + n) = pl;
            }
        }
    }
}

// ---------------- pipelined cp.async tile loaders ----------------
__device__ __forceinline__ void cp_tile128(__nv_bfloat16* dst, const __nv_bfloat16* g,
                                           size_t row0, int kc, int tid) {
    #pragma unroll
    for (int j = 0; j < 2; j++) {
        int idx = tid + j*GTHR;              // 0..511
        int r = idx >> 2, q = idx & 3;
        cp16(dst + r*SK2 + q*8, g + (row0 + r)*(size_t)KPAD + kc + q*8);
    }
}

// ---------------- main GEMM (pipelined): S = A @ W^T + alb ----------------
__global__ __launch_bounds__(GTHR, 2) void gemm_kernel(const float* __restrict__ alb) {
    extern __shared__ __nv_bfloat16 gsm[];
    int tid = threadIdx.x;
    int lane = tid & 31;
    int wid = tid >> 5;
    int wm = wid & 3;
    int wn = wid >> 2;
    int n0 = blockIdx.x * 128;
    size_t m0 = (size_t)blockIdx.y * 128;

    float acc[2][8][4];
    #pragma unroll
    for (int mi = 0; mi < 2; mi++)
        #pragma unroll
        for (int ni = 0; ni < 8; ni++)
            #pragma unroll
            for (int k = 0; k < 4; k++) acc[mi][ni][k] = 0.f;

    int lr = lane & 15;
    int lc = (lane >> 4) * 8;

    // prefetch chunk 0
    {
        __nv_bfloat16* b = gsm;
        cp_tile128(b,           g_Ah, m0, 0, tid);
        cp_tile128(b + BUF_T,   g_Al, m0, 0, tid);
        cp_tile128(b + 2*BUF_T, g_Wh, n0, 0, tid);
        cp_tile128(b + 3*BUF_T, g_Wl, n0, 0, tid);
        CP_COMMIT();
    }

    for (int ch = 0; ch < NCH; ch++) {
        if (ch + 1 < NCH) {
            __nv_bfloat16* b = gsm + ((ch+1)&1)*GEMM2_BUF;
            int kc = (ch+1)*KC;
            cp_tile128(b,           g_Ah, m0, kc, tid);
            cp_tile128(b + BUF_T,   g_Al, m0, kc, tid);
            cp_tile128(b + 2*BUF_T, g_Wh, n0, kc, tid);
            cp_tile128(b + 3*BUF_T, g_Wl, n0, kc, tid);
            CP_COMMIT();
            CP_WAIT1();
        } else {
            CP_WAIT0();
        }
        __syncthreads();
        __nv_bfloat16* sAh = gsm + (ch&1)*GEMM2_BUF;
        __nv_bfloat16* sAl = sAh + BUF_T;
        __nv_bfloat16* sWh = sAh + 2*BUF_T;
        __nv_bfloat16* sWl = sAh + 3*BUF_T;
        #pragma unroll
        for (int ks = 0; ks < 2; ks++) {
            int col = ks*16 + lc;
            uint32_t ah[2][4], al[2][4];
            #pragma unroll
            for (int mi = 0; mi < 2; mi++) {
                int row = wm*32 + mi*16 + lr;
                ldsm4(ah[mi], (uint32_t)__cvta_generic_to_shared(sAh + row*SK2 + col));
                ldsm4(al[mi], (uint32_t)__cvta_generic_to_shared(sAl + row*SK2 + col));
            }
            #pragma unroll
            for (int nb = 0; nb < 4; nb++) {
                int nrow = wn*64 + nb*16 + lr;
                uint32_t wbh[4], wbl[4];
                ldsm4(wbh, (uint32_t)__cvta_generic_to_shared(sWh + nrow*SK2 + col));
                ldsm4(wbl, (uint32_t)__cvta_generic_to_shared(sWl + nrow*SK2 + col));
                #pragma unroll
                for (int mi = 0; mi < 2; mi++) {
                    mma16816(acc[mi][2*nb],   ah[mi], wbh[0], wbh[2]);
                    mma16816(acc[mi][2*nb+1], ah[mi], wbh[1], wbh[3]);
                    mma16816(acc[mi][2*nb],   ah[mi], wbl[0], wbl[2]);
                    mma16816(acc[mi][2*nb+1], ah[mi], wbl[1], wbl[3]);
                    mma16816(acc[mi][2*nb],   al[mi], wbh[0], wbh[2]);
                    mma16816(acc[mi][2*nb+1], al[mi], wbh[1], wbh[3]);
                }
            }
        }
        __syncthreads();
    }

    #pragma unroll
    for (int mi = 0; mi < 2; mi++) {
        #pragma unroll
        for (int ni = 0; ni < 8; ni++) {
            int n = n0 + wn*64 + ni*8 + (lane & 3)*2;
            #pragma unroll
            for (int half = 0; half < 2; half++) {
                size_t m = m0 + wm*32 + mi*16 + (lane >> 2) + half*8;
                if (n + 1 < NPIX) {
                    float2 o;
                    o.x = acc[mi][ni][2*half]   + alb[n];
                    o.y = acc[mi][ni][2*half+1] + alb[n+1];
                    *(float2*)(g_S + m*NPIX + n) = o;
                } else if (n < NPIX) {
                    g_S[m*NPIX + n] = acc[mi][ni][2*half] + alb[n];
                }
            }
        }
    }
}

// ---------------- softmax: g_S -> P bf16 hi/lo into g_Ah/g_Al ----------------
__global__ __launch_bounds__(256) void softmax_kernel() {
    size_t row = (size_t)blockIdx.x*8 + (threadIdx.x >> 5);
    int lane = threadIdx.x & 31;
    const float* S = g_S + row*NPIX;
    __nv_bfloat16* Ph = g_Ah + row*KPAD;
    __nv_bfloat16* Pl = g_Al + row*KPAD;
    float v[19];
    float m = -1e30f;
    #pragma unroll
    for (int i = 0; i < 19; i++) {
        int j = lane + 32*i;
        v[i] = (j < NPIX) ? S[j] : -1e30f;
        m = fmaxf(m, v[i]);
    }
    #pragma unroll
    for (int o = 16; o; o >>= 1) m = fmaxf(m, __shfl_xor_sync(0xffffffffu, m, o));
    float s = 0.f;
    #pragma unroll
    for (int i = 0; i < 19; i++) {
        v[i] = __expf(v[i] - m);
        s += v[i];
    }
    #pragma unroll
    for (int o = 16; o; o >>= 1) s += __shfl_xor_sync(0xffffffffu, s, o);
    float inv = 1.f / s;
    #pragma unroll
    for (int i = 0; i < 19; i++) {
        int j = lane + 32*i;
        if (j < NPIX) {
            float pv = v[i]*inv;
            __nv_bfloat16 h = __float2bfloat16(pv);
            Ph[j] = h;
            Pl[j] = __float2bfloat16(pv - __bfloat162float(h));
        } else {
            Ph[j] = __float2bfloat16(0.f);
            Pl[j] = __float2bfloat16(0.f);
        }
    }
    {
        int j = 608 + lane;
        Ph[j] = __float2bfloat16(0.f);
        Pl[j] = __float2bfloat16(0.f);
    }
}

// ---------------- E GEMM (pipelined): E = P @ Vt^T per bh ----------------
__global__ __launch_bounds__(GTHR, 2) void e_gemm_kernel() {
    extern __shared__ __nv_bfloat16 esm[];
    int tid = threadIdx.x;
    int lane = tid & 31;
    int wid = tid >> 5;
    int mt = blockIdx.x;
    int bhid = blockIdx.y;
    int p00 = mt * 128;
    int bb = bhid >> 2, h = bhid & 3;

    float acc[8][4];
    #pragma unroll
    for (int ni = 0; ni < 8; ni++)
        #pragma unroll
        for (int k = 0; k < 4; k++) acc[ni][k] = 0.f;

    int lr = lane & 15;
    int lc = (lane >> 4) * 8;

    // loaders
    auto loadP = [&](__nv_bfloat16* dPh, __nv_bfloat16* dPl, int kc) {
        #pragma unroll
        for (int j = 0; j < 2; j++) {
            int idx = tid + j*GTHR;
            int r = idx >> 2, q = idx & 3;
            int p = p00 + r; if (p > NPIX-1) p = NPIX-1;
            size_t row = (size_t)bhid*NPIX + p;
            cp16(dPh + r*SK2 + q*8, g_Ah + row*KPAD + kc + q*8);
            cp16(dPl + r*SK2 + q*8, g_Al + row*KPAD + kc + q*8);
        }
    };
    auto loadV = [&](__nv_bfloat16* dVh, __nv_bfloat16* dVl, int kc) {
        int r = tid >> 2, q = tid & 3;     // 256 threads = 64 rows x 4
        size_t row = (size_t)bhid*DH + r;
        cp16(dVh + r*SK2 + q*8, g_Vth + row*KPAD + kc + q*8);
        cp16(dVl + r*SK2 + q*8, g_Vtl + row*KPAD + kc + q*8);
    };

    {
        __nv_bfloat16* b = esm;
        loadP(b, b + BUF_T, 0);
        loadV(b + 2*BUF_T, b + 2*BUF_T + VBUF_T, 0);
        CP_COMMIT();
    }

    for (int ch = 0; ch < NCH; ch++) {
        if (ch + 1 < NCH) {
            __nv_bfloat16* b = esm + ((ch+1)&1)*EBUF;
            int kc = (ch+1)*KC;
            loadP(b, b + BUF_T, kc);
            loadV(b + 2*BUF_T, b + 2*BUF_T + VBUF_T, kc);
            CP_COMMIT();
            CP_WAIT1();
        } else {
            CP_WAIT0();
        }
        __syncthreads();
        __nv_bfloat16* sPh = esm + (ch&1)*EBUF;
        __nv_bfloat16* sPl = sPh + BUF_T;
        __nv_bfloat16* sVh = sPh + 2*BUF_T;
        __nv_bfloat16* sVl = sPh + 2*BUF_T + VBUF_T;
        #pragma unroll
        for (int ks = 0; ks < 2; ks++) {
            int col = ks*16 + lc;
            uint32_t ph[4], pl[4];
            int row = wid*16 + lr;
            ldsm4(ph, (uint32_t)__cvta_generic_to_shared(sPh + row*SK2 + col));
            ldsm4(pl, (uint32_t)__cvta_generic_to_shared(sPl + row*SK2 + col));
            #pragma unroll
            for (int nb = 0; nb < 4; nb++) {
                int nrow = nb*16 + lr;
                uint32_t vbh[4], vbl[4];
                ldsm4(vbh, (uint32_t)__cvta_generic_to_shared(sVh + nrow*SK2 + col));
                ldsm4(vbl, (uint32_t)__cvta_generic_to_shared(sVl + nrow*SK2 + col));
                mma16816(acc[2*nb],   ph, vbh[0], vbh[2]);
                mma16816(acc[2*nb+1], ph, vbh[1], vbh[3]);
                mma16816(acc[2*nb],   ph, vbl[0], vbl[2]);
                mma16816(acc[2*nb+1], ph, vbl[1], vbl[3]);
                mma16816(acc[2*nb],   pl, vbh[0], vbh[2]);
                mma16816(acc[2*nb+1], pl, vbh[1], vbh[3]);
            }
        }
        __syncthreads();
    }

    #pragma unroll
    for (int ni = 0; ni < 8; ni++) {
        int d = ni*8 + (lane & 3)*2;
        #pragma unroll
        for (int half = 0; half < 2; half++) {
            int p = p00 + wid*16 + (lane >> 2) + half*8;
            if (p < NPIX) {
                float2 o; o.x = acc[ni][2*half]; o.y = acc[ni][2*half+1];
                *(float2*)(g_E + ((size_t)bb*NPIX + p)*256 + h*DH + d) = o;
            }
        }
    }
}

// ---------------- lin1 + relu ----------------
__global__ void lin1_kernel(const float* __restrict__ w, const float* __restrict__ b) {
    int idx = blockIdx.x * blockDim.x + threadIdx.x;
    if (idx >= NB*NPIX*DH) return;
    int d = idx & 63;
    int bp = idx >> 6;
    const float* e = g_E + (size_t)bp*256;
    float acc = b[d];
    #pragma unroll 8
    for (int c = 0; c < 256; c++) acc += e[c] * w[c*DH + d];
    g_F[idx] = fmaxf(acc, 0.f);
}

// ---------------- LN2 stats ----------------
__global__ void ln2_stats_kernel() {
    int bb = blockIdx.x;
    const float4* base = (const float4*)(g_F + bb*NPIX*DH);
    const int n4 = NPIX*DH/4;
    float s = 0.f, ss = 0.f;
    for (int i = threadIdx.x; i < n4; i += blockDim.x) {
        float4 v = base[i];
        s  += v.x + v.y + v.z + v.w;
        ss += v.x*v.x + v.y*v.y + v.z*v.z + v.w*v.w;
    }
    __shared__ double sh[256], sh2[256];
    sh[threadIdx.x] = (double)s; sh2[threadIdx.x] = (double)ss; __syncthreads();
    for (int o = 128; o; o >>= 1) {
        if (threadIdx.x < o) { sh[threadIdx.x] += sh[threadIdx.x+o]; sh2[threadIdx.x] += sh2[threadIdx.x+o]; }
        __syncthreads();
    }
    if (threadIdx.x == 0) {
        const int n = NPIX*DH;
        double m = sh[0] / (double)n;
        double var = sh2[0] / (double)n - m*m;
        g_mu2[bb] = (float)m;
        g_rv2[bb] = (float)(1.0 / sqrt(var + 1e-5));
    }
}

// ---------------- LN2 apply + max ----------------
__global__ void ln2max_kernel() {
    int bb = blockIdx.x;
    int d = threadIdx.x & 63, pc = threadIdx.x >> 6;
    float mu = g_mu2[bb], rv = g_rv2[bb];
    float m = -1e30f;
    for (int p = pc; p < NPIX; p += 4) {
        float v = (g_F[(bb*NPIX + p)*DH + d] - mu) * rv;
        m = fmaxf(m, v);
    }
    __shared__ float sh[256];
    sh[threadIdx.x] = m; __syncthreads();
    if (pc == 0) {
        m = fmaxf(fmaxf(sh[d], sh[64+d]), fmaxf(sh[128+d], sh[192+d]));
        g_M[bb*DH + d] = m;
    }
}

// ---------------- final lin2 + elu ----------------
__global__ void final_kernel(const float* __restrict__ w, const float* __restrict__ b,
                             float* __restrict__ out) {
    int idx = blockIdx.x * blockDim.x + threadIdx.x;
    if (idx >= NB*10) return;
    int bb = idx / 10, j = idx % 10;
    float acc = b[j];
    #pragma unroll
    for (int d = 0; d < DH; d++) acc += g_M[bb*DH + d] * w[d*10 + j];
    out[idx] = eluf(acc);
}

extern "C" void kernel_launch(void* const* d_in, const int* in_sizes, int n_in,
                              void* d_out, int out_size) {
    const float* x       = (const float*)d_in[0];
    const float* conv1_w = (const float*)d_in[1];
    const float* conv1_b = (const float*)d_in[2];
    const float* conv2_w = (const float*)d_in[3];
    const float* conv2_b = (const float*)d_in[4];
    const float* kp_w    = (const float*)d_in[5];
    const float* kp_b    = (const float*)d_in[6];
    const float* qp_w    = (const float*)d_in[7];
    const float* qp_b    = (const float*)d_in[8];
    const float* vp_w    = (const float*)d_in[9];
    const float* vp_b    = (const float*)d_in[10];
    const float* klin_w  = (const float*)d_in[11];
    const float* klin_b  = (const float*)d_in[12];
    const float* qlin_w  = (const float*)d_in[13];
    const float* qlin_b  = (const float*)d_in[14];
    const float* alin_w  = (const float*)d_in[15];
    const float* alin_b  = (const float*)d_in[16];
    const float* knorm_g = (const float*)d_in[17];
    const float* knorm_b = (const float*)d_in[18];
    const float* qnorm_g = (const float*)d_in[19];
    const float* qnorm_b = (const float*)d_in[20];
    const float* vnorm_g = (const float*)d_in[21];
    const float* vnorm_b = (const float*)d_in[22];
    const float* lin1_w  = (const float*)d_in[23];
    const float* lin1_b  = (const float*)d_in[24];
    const float* lin2_w  = (const float*)d_in[25];
    const float* lin2_b  = (const float*)d_in[26];
    float* out = (float*)d_out;

    cudaFuncSetAttribute(logits_gemm_kernel, cudaFuncAttributeMaxDynamicSharedMemorySize, GEMM_SMEM);
    cudaFuncSetAttribute(gemm_kernel,        cudaFuncAttributeMaxDynamicSharedMemorySize, GEMM2_SMEM);
    cudaFuncSetAttribute(e_gemm_kernel,      cudaFuncAttributeMaxDynamicSharedMemorySize, EGEMM2_SMEM);

    conv1_kernel<<<(NB*16*150*5 + 255)/256, 256>>>(x, conv1_w, conv1_b);
    conv2_feats_kernel<<<(NB*NPIX*34 + 255)/256, 256>>>(conv2_w, conv2_b);
    {
        dim3 g((NB*NPIX*256 + 255)/256, 3);
        proj_kernel<<<g, 256>>>(kp_w, kp_b, qp_w, qp_b, vp_w, vp_b);
    }
    {
        dim3 g(NB, 3);
        ln_stats_kernel<<<g, 512>>>();
    }
    {
        dim3 g(PER_B/1024, NB, 3);
        ln_apply_kernel<<<g, 256>>>(knorm_g, knorm_b, qnorm_g, qnorm_b, vnorm_g, vnorm_b);
    }
    vtrans_kernel<<<NB*HEADS, 256>>>();
    prepw_kernel<<<(KPAD*KPAD + 255)/256, 256>>>(alin_w);
    prepwqk_kernel<<<(KPAD*128 + 255)/256, 256>>>(qlin_w, klin_w);
    {
        dim3 g(KPAD/128, MROWS/128);               // (5, 1192)
        logits_gemm_kernel<<<g, GTHR, GEMM_SMEM>>>(qlin_b, klin_b);
    }
    {
        dim3 g(KPAD/128, MROWS/128);               // (5, 1192)
        gemm_kernel<<<g, GTHR, GEMM2_SMEM>>>(alin_b);
    }
    softmax_kernel<<<MROWS/8, 256>>>();
    {
        dim3 g(5, NB*HEADS);                       // (5, 256)
        e_gemm_kernel<<<g, GTHR, EGEMM2_SMEM>>>();
    }
    lin1_kernel<<<(NB*NPIX*DH + 255)/256, 256>>>(lin1_w, lin1_b);
    ln2_stats_kernel<<<NB, 256>>>();
    ln2max_kernel<<<NB, 256>>>();
    final_kernel<<<3, 256>>>(lin2_w, lin2_b, out);
}

// round 9
// speedup vs baseline: 3.2374x; 1.2749x over previous
#include <cuda_runtime.h>
#include <cuda_bf16.h>
#include <math.h>
#include <stdint.h>

#define NB 64
#define NPIX 596
#define HEADS 4
#define DH 64
#define PER_B (HEADS*NPIX*DH)   // 152576
#define MROWS (NB*HEADS*NPIX)   // 152576
#define KPAD 640

// ---- tf32 gemm common ----
#define GTHR 256
#define KC 32                   // k-chunk in floats
#define NCH (KPAD/KC)           // 20
#define NCHL (128/KC)           // 4 (logits)
#define SKF 36                  // padded fp32 row stride (floats)
#define FBUF (128*SKF)          // one 128-row tile (floats)
#define VFBUF (64*SKF)
#define G_BUF (2*FBUF)                          // A + W tiles
#define GEMM_SMEM (2*G_BUF*4)                   // 73728 B
#define E_BUF (FBUF + VFBUF)
#define EGEMM_SMEM (2*E_BUF*4)                  // 55296 B

// ---------------- scratch ----------------
__device__ float g_conv1[NB*16*150*5];
__device__ float g_feats[NB*NPIX*34];
__device__ float g_K[NB*HEADS*NPIX*DH];
__device__ float g_Q[NB*HEADS*NPIX*DH];
__device__ float g_V[NB*HEADS*NPIX*DH];
__device__ float g_mu[3*NB], g_rv[3*NB];
__device__ float g_QKf[(size_t)MROWS*128];
__device__ float g_Wqkf[(size_t)KPAD*128];
__device__ float g_A[(size_t)MROWS*KPAD];
__device__ float g_Wf[(size_t)KPAD*KPAD];
__device__ float g_Vt[(size_t)NB*HEADS*DH*KPAD];
__device__ float g_S[(size_t)MROWS*NPIX];
__device__ float g_P[(size_t)MROWS*KPAD];
__device__ float g_E[(size_t)NB*NPIX*256];
__device__ float g_F[NB*NPIX*DH];
__device__ float g_mu2[NB], g_rv2[NB];
__device__ float g_M[NB*DH];

__device__ __forceinline__ float eluf(float x) {
    return x > 0.f ? x : (__expf(x) - 1.f);
}
__device__ __forceinline__ float tf32r(float x) {
    uint32_t u;
    asm("cvt.rna.tf32.f32 %0, %1;" : "=r"(u) : "f"(x));
    return __uint_as_float(u);
}

// ---- mma.sync tf32 ----
__device__ __forceinline__ void mma_tf32(float* c, const float* a, float b0, float b1) {
    asm volatile(
        "mma.sync.aligned.m16n8k8.row.col.f32.tf32.tf32.f32 "
        "{%0,%1,%2,%3}, {%4,%5,%6,%7}, {%8,%9}, {%0,%1,%2,%3};"
        : "+f"(c[0]), "+f"(c[1]), "+f"(c[2]), "+f"(c[3])
        : "r"(__float_as_uint(a[0])), "r"(__float_as_uint(a[1])),
          "r"(__float_as_uint(a[2])), "r"(__float_as_uint(a[3])),
          "r"(__float_as_uint(b0)), "r"(__float_as_uint(b1)));
}
// ---- cp.async ----
__device__ __forceinline__ void cp16(void* smem, const void* gmem) {
    uint32_t s = (uint32_t)__cvta_generic_to_shared(smem);
    asm volatile("cp.async.cg.shared.global [%0], [%1], 16;" :: "r"(s), "l"(gmem));
}
#define CP_COMMIT() asm volatile("cp.async.commit_group;" ::: "memory")
#define CP_WAIT1()  asm volatile("cp.async.wait_group 1;" ::: "memory")
#define CP_WAIT0()  asm volatile("cp.async.wait_group 0;" ::: "memory")

// ---------------- conv1 + relu ----------------
__global__ void conv1_kernel(const float* __restrict__ x,
                             const float* __restrict__ w,
                             const float* __restrict__ b) {
    int idx = blockIdx.x * blockDim.x + threadIdx.x;
    if (idx >= NB*16*150*5) return;
    int ow = idx % 5;
    int oh = (idx / 5) % 150;
    int co = (idx / (5*150)) % 16;
    int bb = idx / (5*150*16);
    float acc = b[co];
    #pragma unroll
    for (int ci = 0; ci < 4; ci++)
        #pragma unroll
        for (int kh = 0; kh < 2; kh++)
            #pragma unroll
            for (int kw = 0; kw < 2; kw++)
                acc += x[((bb*4+ci)*151 + oh+kh)*6 + ow+kw] *
                       w[((co*4+ci)*2 + kh)*2 + kw];
    g_conv1[idx] = fmaxf(acc, 0.f);
}

// ---------------- conv2 + relu + coords -> feats ----------------
__global__ void conv2_feats_kernel(const float* __restrict__ w,
                                   const float* __restrict__ b) {
    int idx = blockIdx.x * blockDim.x + threadIdx.x;
    if (idx >= NB*NPIX*34) return;
    int c = idx % 34;
    int p = (idx / 34) % NPIX;
    int bb = idx / (34*NPIX);
    int oh = p / 4, ow = p % 4;
    float val;
    if (c < 32) {
        float acc = b[c];
        #pragma unroll 4
        for (int ci = 0; ci < 16; ci++)
            #pragma unroll
            for (int kh = 0; kh < 2; kh++)
                #pragma unroll
                for (int kw = 0; kw < 2; kw++)
                    acc += g_conv1[((bb*16+ci)*150 + oh+kh)*5 + ow+kw] *
                           w[((c*16+ci)*2 + kh)*2 + kw];
        val = fmaxf(acc, 0.f);
    } else if (c == 32) {
        val = (float)ow / 4.f;
    } else {
        val = (float)oh / 149.f;
    }
    g_feats[idx] = val;
}

// ---------------- K/Q/V projections ----------------
__global__ void proj_kernel(const float* __restrict__ kw, const float* __restrict__ kb,
                            const float* __restrict__ qw, const float* __restrict__ qb,
                            const float* __restrict__ vw, const float* __restrict__ vb) {
    int t = blockIdx.y;
    const float* W = t==0 ? kw : t==1 ? qw : vw;
    const float* B = t==0 ? kb : t==1 ? qb : vb;
    float* O = t==0 ? g_K : t==1 ? g_Q : g_V;
    int idx = blockIdx.x * blockDim.x + threadIdx.x;
    if (idx >= NB*NPIX*256) return;
    int hd = idx & 255;
    int bp = idx >> 8;
    int p = bp % NPIX, bb = bp / NPIX;
    const float* f = g_feats + bp*34;
    float acc = B[hd];
    #pragma unroll
    for (int c = 0; c < 34; c++) acc += f[c] * W[c*256 + hd];
    int h = hd >> 6, d = hd & 63;
    O[((bb*HEADS + h)*NPIX + p)*DH + d] = acc;
}

// ---------------- LN stats (512 thr, float4) ----------------
__global__ __launch_bounds__(512) void ln_stats_kernel() {
    int bb = blockIdx.x, t = blockIdx.y;
    const float4* base = (const float4*)((t==0 ? g_K : t==1 ? g_Q : g_V) + bb*PER_B);
    const int n4 = PER_B/4;
    float s = 0.f, ss = 0.f;
    for (int i = threadIdx.x; i < n4; i += 512) {
        float4 v = base[i];
        s  += v.x + v.y + v.z + v.w;
        ss += v.x*v.x + v.y*v.y + v.z*v.z + v.w*v.w;
    }
    __shared__ double sh[512], sh2[512];
    sh[threadIdx.x] = (double)s; sh2[threadIdx.x] = (double)ss; __syncthreads();
    for (int o = 256; o; o >>= 1) {
        if (threadIdx.x < o) { sh[threadIdx.x] += sh[threadIdx.x+o]; sh2[threadIdx.x] += sh2[threadIdx.x+o]; }
        __syncthreads();
    }
    if (threadIdx.x == 0) {
        double m = sh[0] / (double)PER_B;
        double var = sh2[0] / (double)PER_B - m*m;
        g_mu[t*NB+bb] = (float)m;
        g_rv[t*NB+bb] = (float)(1.0 / sqrt(var + 1e-5));
    }
}

// ---------------- LN apply: Q,K -> tf32-rounded QK concat; V -> fp32 ----------------
__global__ void ln_apply_kernel(const float* __restrict__ kg, const float* __restrict__ kb,
                                const float* __restrict__ qg, const float* __restrict__ qb,
                                const float* __restrict__ vg, const float* __restrict__ vb) {
    int t = blockIdx.z;
    int bb = blockIdx.y;
    const float* base = (t==0 ? g_K : t==1 ? g_Q : g_V) + bb*PER_B;
    const float* g = t==0 ? kg : t==1 ? qg : vg;
    const float* be = t==0 ? kb : t==1 ? qb : vb;
    int off = (blockIdx.x*256 + threadIdx.x)*4;
    float mu = g_mu[t*NB+bb], rv = g_rv[t*NB+bb];
    float4 v  = *(const float4*)(base + off);
    float4 gg = *(const float4*)(g + off);
    float4 bv = *(const float4*)(be + off);
    float4 r;
    r.x = (v.x - mu)*rv*gg.x + bv.x;
    r.y = (v.y - mu)*rv*gg.y + bv.y;
    r.z = (v.z - mu)*rv*gg.z + bv.z;
    r.w = (v.w - mu)*rv*gg.w + bv.w;
    if (t == 2) {
        *(float4*)(g_V + bb*PER_B + off) = r;
    } else {
        int d = off & 63;
        int hp = off >> 6;
        size_t row = (size_t)bb*HEADS*NPIX + hp;
        int col = d + (t == 0 ? 64 : 0);
        float4 o;
        o.x = tf32r(r.x); o.y = tf32r(r.y); o.z = tf32r(r.z); o.w = tf32r(r.w);
        *(float4*)(g_QKf + row*128 + col) = o;
    }
}

// ---------------- V transpose (tf32-rounded): Vt[bh][d][p_pad] ----------------
__global__ void vtrans_kernel() {
    __shared__ float tile[32][65];
    int bhid = blockIdx.x;
    const float* Vb = g_V + (size_t)bhid*NPIX*DH;
    int t = threadIdx.x;
    for (int pt = 0; pt < 20; pt++) {
        int p0 = pt*32;
        for (int i = t; i < 32*64; i += 256) {
            int r = i >> 6, c = i & 63;
            tile[r][c] = (p0 + r < NPIX) ? Vb[(p0 + r)*DH + c] : 0.f;
        }
        __syncthreads();
        for (int i = t; i < 64*32; i += 256) {
            int d = i >> 5, pp = i & 31;
            g_Vt[((size_t)bhid*DH + d)*KPAD + p0 + pp] = tf32r(tile[pp][d]);
        }
        __syncthreads();
    }
}

// ---------------- prep: alin_w transposed, tf32-rounded ----------------
__global__ void prepw_kernel(const float* __restrict__ alw) {
    int idx = blockIdx.x*256 + threadIdx.x;
    if (idx >= KPAD*KPAD) return;
    int k = idx / KPAD, n = idx % KPAD;
    float v = (k < NPIX && n < NPIX) ? alw[k*NPIX + n] : 0.f;
    g_Wf[(size_t)n*KPAD + k] = tf32r(v);
}

// ---------------- prep: [qlw;klw] transposed, tf32-rounded ----------------
__global__ void prepwqk_kernel(const float* __restrict__ qlw, const float* __restrict__ klw) {
    int idx = blockIdx.x*256 + threadIdx.x;
    if (idx >= KPAD*128) return;
    int n = idx >> 7, k = idx & 127;
    float v = 0.f;
    if (n < NPIX) v = (k < 64) ? qlw[k*NPIX + n] : klw[(k-64)*NPIX + n];
    g_Wqkf[(size_t)n*128 + k] = tf32r(v);
}

// ---------------- pipelined cp.async tile loaders (fp32) ----------------
__device__ __forceinline__ void cp_ftile128(float* dst, const float* g,
                                            size_t row0, int kc, int tid, int gstride) {
    #pragma unroll
    for (int j = 0; j < 4; j++) {
        int idx = tid + j*GTHR;              // 0..1023
        int r = idx >> 3, q = idx & 7;
        cp16(dst + r*SKF + q*4, g + (row0 + r)*(size_t)gstride + kc + q*4);
    }
}

// ---------------- tf32 GEMM inner step (one k8) ----------------
// A smem: [128][SKF] rows m; W smem: [128][SKF] rows n.
// returns via acc[mi][nsub][4]
__device__ __forceinline__ void tf32_step(const float* sA, const float* sW, int ko,
                                          int wm, int wn, int g, int tig,
                                          float acc[2][8][4]) {
    float af[2][4];
    #pragma unroll
    for (int mi = 0; mi < 2; mi++) {
        const float* ar = sA + (wm*32 + mi*16 + g)*SKF + ko + tig;
        af[mi][0] = ar[0];
        af[mi][1] = ar[8*SKF];
        af[mi][2] = ar[4];
        af[mi][3] = ar[8*SKF + 4];
    }
    #pragma unroll
    for (int nsub = 0; nsub < 8; nsub++) {
        const float* br = sW + (wn*64 + nsub*8 + g)*SKF + ko + tig;
        float b0 = br[0], b1 = br[4];
        mma_tf32(acc[0][nsub], af[0], b0, b1);
        mma_tf32(acc[1][nsub], af[1], b0, b1);
    }
}

// ---------------- logits GEMM (tf32): A = elu(QK @ Wqk^T + bias) -> g_A ----------------
__global__ __launch_bounds__(GTHR, 2) void logits_gemm_kernel(
    const float* __restrict__ qlb, const float* __restrict__ klb) {
    extern __shared__ float fsm[];
    int tid = threadIdx.x;
    int lane = tid & 31;
    int wid = tid >> 5;
    int wm = wid & 3, wn = wid >> 2;
    int g = lane >> 2, tig = lane & 3;
    int n0 = blockIdx.x * 128;
    size_t m0 = (size_t)blockIdx.y * 128;

    float acc[2][8][4];
    #pragma unroll
    for (int mi = 0; mi < 2; mi++)
        #pragma unroll
        for (int ni = 0; ni < 8; ni++)
            #pragma unroll
            for (int k = 0; k < 4; k++) acc[mi][ni][k] = 0.f;

    {
        float* b = fsm;
        cp_ftile128(b,        g_QKf,  m0, 0, tid, 128);
        cp_ftile128(b + FBUF, g_Wqkf, n0, 0, tid, 128);
        CP_COMMIT();
    }
    for (int ch = 0; ch < NCHL; ch++) {
        if (ch + 1 < NCHL) {
            float* b = fsm + ((ch+1)&1)*G_BUF;
            int kc = (ch+1)*KC;
            cp_ftile128(b,        g_QKf,  m0, kc, tid, 128);
            cp_ftile128(b + FBUF, g_Wqkf, n0, kc, tid, 128);
            CP_COMMIT();
            CP_WAIT1();
        } else {
            CP_WAIT0();
        }
        __syncthreads();
        const float* sA = fsm + (ch&1)*G_BUF;
        const float* sW = sA + FBUF;
        #pragma unroll
        for (int ks = 0; ks < 4; ks++)
            tf32_step(sA, sW, ks*8, wm, wn, g, tig, acc);
        __syncthreads();
    }

    #pragma unroll
    for (int mi = 0; mi < 2; mi++) {
        #pragma unroll
        for (int nsub = 0; nsub < 8; nsub++) {
            int n = n0 + wn*64 + nsub*8 + tig*2;
            float b0 = (n < NPIX)   ? qlb[n] + klb[n]     : 0.f;
            float b1 = (n+1 < NPIX) ? qlb[n+1] + klb[n+1] : 0.f;
            #pragma unroll
            for (int half = 0; half < 2; half++) {
                size_t m = m0 + wm*32 + mi*16 + g + half*8;
                float2 o;
                o.x = tf32r(eluf(acc[mi][nsub][2*half]   + b0));
                o.y = tf32r(eluf(acc[mi][nsub][2*half+1] + b1));
                *(float2*)(g_A + m*KPAD + n) = o;
            }
        }
    }
}

// ---------------- main GEMM (tf32): S = A @ W^T + alb ----------------
__global__ __launch_bounds__(GTHR, 2) void gemm_kernel(const float* __restrict__ alb) {
    extern __shared__ float fsm[];
    int tid = threadIdx.x;
    int lane = tid & 31;
    int wid = tid >> 5;
    int wm = wid & 3, wn = wid >> 2;
    int g = lane >> 2, tig = lane & 3;
    int n0 = blockIdx.x * 128;
    size_t m0 = (size_t)blockIdx.y * 128;

    float acc[2][8][4];
    #pragma unroll
    for (int mi = 0; mi < 2; mi++)
        #pragma unroll
        for (int ni = 0; ni < 8; ni++)
            #pragma unroll
            for (int k = 0; k < 4; k++) acc[mi][ni][k] = 0.f;

    {
        float* b = fsm;
        cp_ftile128(b,        g_A,  m0, 0, tid, KPAD);
        cp_ftile128(b + FBUF, g_Wf, n0, 0, tid, KPAD);
        CP_COMMIT();
    }
    for (int ch = 0; ch < NCH; ch++) {
        if (ch + 1 < NCH) {
            float* b = fsm + ((ch+1)&1)*G_BUF;
            int kc = (ch+1)*KC;
            cp_ftile128(b,        g_A,  m0, kc, tid, KPAD);
            cp_ftile128(b + FBUF, g_Wf, n0, kc, tid, KPAD);
            CP_COMMIT();
            CP_WAIT1();
        } else {
            CP_WAIT0();
        }
        __syncthreads();
        const float* sA = fsm + (ch&1)*G_BUF;
        const float* sW = sA + FBUF;
        #pragma unroll
        for (int ks = 0; ks < 4; ks++)
            tf32_step(sA, sW, ks*8, wm, wn, g, tig, acc);
        __syncthreads();
    }

    #pragma unroll
    for (int mi = 0; mi < 2; mi++) {
        #pragma unroll
        for (int nsub = 0; nsub < 8; nsub++) {
            int n = n0 + wn*64 + nsub*8 + tig*2;
            #pragma unroll
            for (int half = 0; half < 2; half++) {
                size_t m = m0 + wm*32 + mi*16 + g + half*8;
                if (n + 1 < NPIX) {
                    float2 o;
                    o.x = acc[mi][nsub][2*half]   + alb[n];
                    o.y = acc[mi][nsub][2*half+1] + alb[n+1];
                    *(float2*)(g_S + m*NPIX + n) = o;
                } else if (n < NPIX) {
                    g_S[m*NPIX + n] = acc[mi][nsub][2*half] + alb[n];
                }
            }
        }
    }
}

// ---------------- softmax: g_S -> g_P (tf32-rounded, zero-padded) ----------------
__global__ __launch_bounds__(256) void softmax_kernel() {
    size_t row = (size_t)blockIdx.x*8 + (threadIdx.x >> 5);
    int lane = threadIdx.x & 31;
    const float* S = g_S + row*NPIX;
    float* P = g_P + row*KPAD;
    float v[19];
    float m = -1e30f;
    #pragma unroll
    for (int i = 0; i < 19; i++) {
        int j = lane + 32*i;
        v[i] = (j < NPIX) ? S[j] : -1e30f;
        m = fmaxf(m, v[i]);
    }
    #pragma unroll
    for (int o = 16; o; o >>= 1) m = fmaxf(m, __shfl_xor_sync(0xffffffffu, m, o));
    float s = 0.f;
    #pragma unroll
    for (int i = 0; i < 19; i++) {
        v[i] = __expf(v[i] - m);
        s += v[i];
    }
    #pragma unroll
    for (int o = 16; o; o >>= 1) s += __shfl_xor_sync(0xffffffffu, s, o);
    float inv = 1.f / s;
    #pragma unroll
    for (int i = 0; i < 19; i++) {
        int j = lane + 32*i;
        if (j < NPIX) P[j] = tf32r(v[i]*inv);
        else          P[j] = 0.f;
    }
    P[608 + lane] = 0.f;
}

// ---------------- E GEMM (tf32): E = P @ Vt^T per bh ----------------
__global__ __launch_bounds__(GTHR, 2) void e_gemm_kernel() {
    extern __shared__ float fsm[];
    int tid = threadIdx.x;
    int lane = tid & 31;
    int wid = tid >> 5;
    int g = lane >> 2, tig = lane & 3;
    int mt = blockIdx.x;
    int bhid = blockIdx.y;
    int p00 = mt * 128;
    int bb = bhid >> 2, h = bhid & 3;

    float acc[8][4];
    #pragma unroll
    for (int ni = 0; ni < 8; ni++)
        #pragma unroll
        for (int k = 0; k < 4; k++) acc[ni][k] = 0.f;

    auto loadT = [&](float* b, int kc) {
        #pragma unroll
        for (int j = 0; j < 4; j++) {
            int idx = tid + j*GTHR;
            int r = idx >> 3, q = idx & 7;
            int p = p00 + r; if (p > NPIX-1) p = NPIX-1;
            cp16(b + r*SKF + q*4, g_P + ((size_t)bhid*NPIX + p)*KPAD + kc + q*4);
        }
        #pragma unroll
        for (int j = 0; j < 2; j++) {
            int idx = tid + j*GTHR;
            int r = idx >> 3, q = idx & 7;
            cp16(b + FBUF + r*SKF + q*4, g_Vt + ((size_t)bhid*DH + r)*KPAD + kc + q*4);
        }
    };

    loadT(fsm, 0);
    CP_COMMIT();
    for (int ch = 0; ch < NCH; ch++) {
        if (ch + 1 < NCH) {
            loadT(fsm + ((ch+1)&1)*E_BUF, (ch+1)*KC);
            CP_COMMIT();
            CP_WAIT1();
        } else {
            CP_WAIT0();
        }
        __syncthreads();
        const float* sP = fsm + (ch&1)*E_BUF;
        const float* sV = sP + FBUF;
        #pragma unroll
        for (int ks = 0; ks < 4; ks++) {
            int ko = ks*8;
            float af[4];
            const float* ar = sP + (wid*16 + g)*SKF + ko + tig;
            af[0] = ar[0];
            af[1] = ar[8*SKF];
            af[2] = ar[4];
            af[3] = ar[8*SKF + 4];
            #pragma unroll
            for (int nsub = 0; nsub < 8; nsub++) {
                const float* br = sV + (nsub*8 + g)*SKF + ko + tig;
                mma_tf32(acc[nsub], af, br[0], br[4]);
            }
        }
        __syncthreads();
    }

    #pragma unroll
    for (int nsub = 0; nsub < 8; nsub++) {
        int d = nsub*8 + tig*2;
        #pragma unroll
        for (int half = 0; half < 2; half++) {
            int p = p00 + wid*16 + g + half*8;
            if (p < NPIX) {
                float2 o; o.x = acc[nsub][2*half]; o.y = acc[nsub][2*half+1];
                *(float2*)(g_E + ((size_t)bb*NPIX + p)*256 + h*DH + d) = o;
            }
        }
    }
}

// ---------------- lin1 + relu ----------------
__global__ void lin1_kernel(const float* __restrict__ w, const float* __restrict__ b) {
    int idx = blockIdx.x * blockDim.x + threadIdx.x;
    if (idx >= NB*NPIX*DH) return;
    int d = idx & 63;
    int bp = idx >> 6;
    const float* e = g_E + (size_t)bp*256;
    float acc = b[d];
    #pragma unroll 8
    for (int c = 0; c < 256; c++) acc += e[c] * w[c*DH + d];
    g_F[idx] = fmaxf(acc, 0.f);
}

// ---------------- LN2 stats ----------------
__global__ void ln2_stats_kernel() {
    int bb = blockIdx.x;
    const float4* base = (const float4*)(g_F + bb*NPIX*DH);
    const int n4 = NPIX*DH/4;
    float s = 0.f, ss = 0.f;
    for (int i = threadIdx.x; i < n4; i += blockDim.x) {
        float4 v = base[i];
        s  += v.x + v.y + v.z + v.w;
        ss += v.x*v.x + v.y*v.y + v.z*v.z + v.w*v.w;
    }
    __shared__ double sh[256], sh2[256];
    sh[threadIdx.x] = (double)s; sh2[threadIdx.x] = (double)ss; __syncthreads();
    for (int o = 128; o; o >>= 1) {
        if (threadIdx.x < o) { sh[threadIdx.x] += sh[threadIdx.x+o]; sh2[threadIdx.x] += sh2[threadIdx.x+o]; }
        __syncthreads();
    }
    if (threadIdx.x == 0) {
        const int n = NPIX*DH;
        double m = sh[0] / (double)n;
        double var = sh2[0] / (double)n - m*m;
        g_mu2[bb] = (float)m;
        g_rv2[bb] = (float)(1.0 / sqrt(var + 1e-5));
    }
}

// ---------------- LN2 apply + max ----------------
__global__ void ln2max_kernel() {
    int bb = blockIdx.x;
    int d = threadIdx.x & 63, pc = threadIdx.x >> 6;
    float mu = g_mu2[bb], rv = g_rv2[bb];
    float m = -1e30f;
    for (int p = pc; p < NPIX; p += 4) {
        float v = (g_F[(bb*NPIX + p)*DH + d] - mu) * rv;
        m = fmaxf(m, v);
    }
    __shared__ float sh[256];
    sh[threadIdx.x] = m; __syncthreads();
    if (pc == 0) {
        m = fmaxf(fmaxf(sh[d], sh[64+d]), fmaxf(sh[128+d], sh[192+d]));
        g_M[bb*DH + d] = m;
    }
}

// ---------------- final lin2 + elu ----------------
__global__ void final_kernel(const float* __restrict__ w, const float* __restrict__ b,
                             float* __restrict__ out) {
    int idx = blockIdx.x * blockDim.x + threadIdx.x;
    if (idx >= NB*10) return;
    int bb = idx / 10, j = idx % 10;
    float acc = b[j];
    #pragma unroll
    for (int d = 0; d < DH; d++) acc += g_M[bb*DH + d] * w[d*10 + j];
    out[idx] = eluf(acc);
}

extern "C" void kernel_launch(void* const* d_in, const int* in_sizes, int n_in,
                              void* d_out, int out_size) {
    const float* x       = (const float*)d_in[0];
    const float* conv1_w = (const float*)d_in[1];
    const float* conv1_b = (const float*)d_in[2];
    const float* conv2_w = (const float*)d_in[3];
    const float* conv2_b = (const float*)d_in[4];
    const float* kp_w    = (const float*)d_in[5];
    const float* kp_b    = (const float*)d_in[6];
    const float* qp_w    = (const float*)d_in[7];
    const float* qp_b    = (const float*)d_in[8];
    const float* vp_w    = (const float*)d_in[9];
    const float* vp_b    = (const float*)d_in[10];
    const float* klin_w  = (const float*)d_in[11];
    const float* klin_b  = (const float*)d_in[12];
    const float* qlin_w  = (const float*)d_in[13];
    const float* qlin_b  = (const float*)d_in[14];
    const float* alin_w  = (const float*)d_in[15];
    const float* alin_b  = (const float*)d_in[16];
    const float* knorm_g = (const float*)d_in[17];
    const float* knorm_b = (const float*)d_in[18];
    const float* qnorm_g = (const float*)d_in[19];
    const float* qnorm_b = (const float*)d_in[20];
    const float* vnorm_g = (const float*)d_in[21];
    const float* vnorm_b = (const float*)d_in[22];
    const float* lin1_w  = (const float*)d_in[23];
    const float* lin1_b  = (const float*)d_in[24];
    const float* lin2_w  = (const float*)d_in[25];
    const float* lin2_b  = (const float*)d_in[26];
    float* out = (float*)d_out;

    cudaFuncSetAttribute(logits_gemm_kernel, cudaFuncAttributeMaxDynamicSharedMemorySize, GEMM_SMEM);
    cudaFuncSetAttribute(gemm_kernel,        cudaFuncAttributeMaxDynamicSharedMemorySize, GEMM_SMEM);
    cudaFuncSetAttribute(e_gemm_kernel,      cudaFuncAttributeMaxDynamicSharedMemorySize, EGEMM_SMEM);

    conv1_kernel<<<(NB*16*150*5 + 255)/256, 256>>>(x, conv1_w, conv1_b);
    conv2_feats_kernel<<<(NB*NPIX*34 + 255)/256, 256>>>(conv2_w, conv2_b);
    {
        dim3 g((NB*NPIX*256 + 255)/256, 3);
        proj_kernel<<<g, 256>>>(kp_w, kp_b, qp_w, qp_b, vp_w, vp_b);
    }
    {
        dim3 g(NB, 3);
        ln_stats_kernel<<<g, 512>>>();
    }
    {
        dim3 g(PER_B/1024, NB, 3);
        ln_apply_kernel<<<g, 256>>>(knorm_g, knorm_b, qnorm_g, qnorm_b, vnorm_g, vnorm_b);
    }
    vtrans_kernel<<<NB*HEADS, 256>>>();
    prepw_kernel<<<(KPAD*KPAD + 255)/256, 256>>>(alin_w);
    prepwqk_kernel<<<(KPAD*128 + 255)/256, 256>>>(qlin_w, klin_w);
    {
        dim3 g(KPAD/128, MROWS/128);               // (5, 1192)
        logits_gemm_kernel<<<g, GTHR, GEMM_SMEM>>>(qlin_b, klin_b);
    }
    {
        dim3 g(KPAD/128, MROWS/128);               // (5, 1192)
        gemm_kernel<<<g, GTHR, GEMM_SMEM>>>(alin_b);
    }
    softmax_kernel<<<MROWS/8, 256>>>();
    {
        dim3 g(5, NB*HEADS);                       // (5, 256)
        e_gemm_kernel<<<g, GTHR, EGEMM_SMEM>>>();
    }
    lin1_kernel<<<(NB*NPIX*DH + 255)/256, 256>>>(lin1_w, lin1_b);
    ln2_stats_kernel<<<NB, 256>>>();
    ln2max_kernel<<<NB, 256>>>();
    final_kernel<<<3, 256>>>(lin2_w, lin2_b, out);
}

// round 10
// speedup vs baseline: 3.4879x; 1.0774x over previous
#include <cuda_runtime.h>
#include <cuda_bf16.h>
#include <math.h>
#include <stdint.h>

#define NB 64
#define NPIX 596
#define HEADS 4
#define DH 64
#define PER_B (HEADS*NPIX*DH)   // 152576
#define MROWS (NB*HEADS*NPIX)   // 152576
#define EROWS (NB*NPIX)         // 38144
#define KPAD 640

// ---- tf32 gemm common ----
#define KC 32                   // k-chunk in floats
#define NCH (KPAD/KC)           // 20
#define NCHL (128/KC)           // 4 (logits)
#define NCH1 (256/KC)           // 8 (lin1)
#define SKF 36                  // padded fp32 row stride (floats)
#define FBUF (128*SKF)          // one 128-row tile (floats)
#define VFBUF (64*SKF)
#define G_BUF (2*FBUF)                          // A + W tiles
#define GEMM_SMEM (2*G_BUF*4)                   // 73728 B
#define E_BUF (FBUF + VFBUF)
#define EGEMM_SMEM (2*E_BUF*4)                  // 55296 B

// ---------------- scratch ----------------
__device__ float g_conv1[NB*16*150*5];
__device__ float g_feats[NB*NPIX*34];
__device__ float g_K[NB*HEADS*NPIX*DH];
__device__ float g_Q[NB*HEADS*NPIX*DH];
__device__ float g_V[NB*HEADS*NPIX*DH];
__device__ float g_mu[3*NB], g_rv[3*NB];
__device__ float g_QKf[(size_t)MROWS*128];
__device__ float g_Wqkf[(size_t)KPAD*128];
__device__ float g_A[(size_t)MROWS*KPAD];
__device__ float g_Wf[(size_t)KPAD*KPAD];
__device__ float g_Vt[(size_t)NB*HEADS*DH*KPAD];
__device__ float g_W1t[64*256];
__device__ float g_S[(size_t)MROWS*NPIX];
__device__ float g_P[(size_t)MROWS*KPAD];
__device__ float g_E[(size_t)EROWS*256];
__device__ float g_F[EROWS*DH];
__device__ float g_mu2[NB], g_rv2[NB];
__device__ float g_M[NB*DH];

__device__ __forceinline__ float eluf(float x) {
    return x > 0.f ? x : (__expf(x) - 1.f);
}
__device__ __forceinline__ float tf32r(float x) {
    uint32_t u;
    asm("cvt.rna.tf32.f32 %0, %1;" : "=r"(u) : "f"(x));
    return __uint_as_float(u);
}

// ---- mma.sync tf32 ----
__device__ __forceinline__ void mma_tf32(float* c, const float* a, float b0, float b1) {
    asm volatile(
        "mma.sync.aligned.m16n8k8.row.col.f32.tf32.tf32.f32 "
        "{%0,%1,%2,%3}, {%4,%5,%6,%7}, {%8,%9}, {%0,%1,%2,%3};"
        : "+f"(c[0]), "+f"(c[1]), "+f"(c[2]), "+f"(c[3])
        : "r"(__float_as_uint(a[0])), "r"(__float_as_uint(a[1])),
          "r"(__float_as_uint(a[2])), "r"(__float_as_uint(a[3])),
          "r"(__float_as_uint(b0)), "r"(__float_as_uint(b1)));
}
// ---- cp.async ----
__device__ __forceinline__ void cp16(void* smem, const void* gmem) {
    uint32_t s = (uint32_t)__cvta_generic_to_shared(smem);
    asm volatile("cp.async.cg.shared.global [%0], [%1], 16;" :: "r"(s), "l"(gmem));
}
#define CP_COMMIT() asm volatile("cp.async.commit_group;" ::: "memory")
#define CP_WAIT1()  asm volatile("cp.async.wait_group 1;" ::: "memory")
#define CP_WAIT0()  asm volatile("cp.async.wait_group 0;" ::: "memory")

// ---------------- conv1 + relu ----------------
__global__ void conv1_kernel(const float* __restrict__ x,
                             const float* __restrict__ w,
                             const float* __restrict__ b) {
    int idx = blockIdx.x * blockDim.x + threadIdx.x;
    if (idx >= NB*16*150*5) return;
    int ow = idx % 5;
    int oh = (idx / 5) % 150;
    int co = (idx / (5*150)) % 16;
    int bb = idx / (5*150*16);
    float acc = b[co];
    #pragma unroll
    for (int ci = 0; ci < 4; ci++)
        #pragma unroll
        for (int kh = 0; kh < 2; kh++)
            #pragma unroll
            for (int kw = 0; kw < 2; kw++)
                acc += x[((bb*4+ci)*151 + oh+kh)*6 + ow+kw] *
                       w[((co*4+ci)*2 + kh)*2 + kw];
    g_conv1[idx] = fmaxf(acc, 0.f);
}

// ---------------- conv2 + relu + coords -> feats ----------------
__global__ void conv2_feats_kernel(const float* __restrict__ w,
                                   const float* __restrict__ b) {
    int idx = blockIdx.x * blockDim.x + threadIdx.x;
    if (idx >= NB*NPIX*34) return;
    int c = idx % 34;
    int p = (idx / 34) % NPIX;
    int bb = idx / (34*NPIX);
    int oh = p / 4, ow = p % 4;
    float val;
    if (c < 32) {
        float acc = b[c];
        #pragma unroll 4
        for (int ci = 0; ci < 16; ci++)
            #pragma unroll
            for (int kh = 0; kh < 2; kh++)
                #pragma unroll
                for (int kw = 0; kw < 2; kw++)
                    acc += g_conv1[((bb*16+ci)*150 + oh+kh)*5 + ow+kw] *
                           w[((c*16+ci)*2 + kh)*2 + kw];
        val = fmaxf(acc, 0.f);
    } else if (c == 32) {
        val = (float)ow / 4.f;
    } else {
        val = (float)oh / 149.f;
    }
    g_feats[idx] = val;
}

// ---------------- K/Q/V projections ----------------
__global__ void proj_kernel(const float* __restrict__ kw, const float* __restrict__ kb,
                            const float* __restrict__ qw, const float* __restrict__ qb,
                            const float* __restrict__ vw, const float* __restrict__ vb) {
    int t = blockIdx.y;
    const float* W = t==0 ? kw : t==1 ? qw : vw;
    const float* B = t==0 ? kb : t==1 ? qb : vb;
    float* O = t==0 ? g_K : t==1 ? g_Q : g_V;
    int idx = blockIdx.x * blockDim.x + threadIdx.x;
    if (idx >= NB*NPIX*256) return;
    int hd = idx & 255;
    int bp = idx >> 8;
    int p = bp % NPIX, bb = bp / NPIX;
    const float* f = g_feats + bp*34;
    float acc = B[hd];
    #pragma unroll
    for (int c = 0; c < 34; c++) acc += f[c] * W[c*256 + hd];
    int h = hd >> 6, d = hd & 63;
    O[((bb*HEADS + h)*NPIX + p)*DH + d] = acc;
}

// ---------------- LN stats (512 thr, float4) ----------------
__global__ __launch_bounds__(512) void ln_stats_kernel() {
    int bb = blockIdx.x, t = blockIdx.y;
    const float4* base = (const float4*)((t==0 ? g_K : t==1 ? g_Q : g_V) + bb*PER_B);
    const int n4 = PER_B/4;
    float s = 0.f, ss = 0.f;
    for (int i = threadIdx.x; i < n4; i += 512) {
        float4 v = base[i];
        s  += v.x + v.y + v.z + v.w;
        ss += v.x*v.x + v.y*v.y + v.z*v.z + v.w*v.w;
    }
    __shared__ double sh[512], sh2[512];
    sh[threadIdx.x] = (double)s; sh2[threadIdx.x] = (double)ss; __syncthreads();
    for (int o = 256; o; o >>= 1) {
        if (threadIdx.x < o) { sh[threadIdx.x] += sh[threadIdx.x+o]; sh2[threadIdx.x] += sh2[threadIdx.x+o]; }
        __syncthreads();
    }
    if (threadIdx.x == 0) {
        double m = sh[0] / (double)PER_B;
        double var = sh2[0] / (double)PER_B - m*m;
        g_mu[t*NB+bb] = (float)m;
        g_rv[t*NB+bb] = (float)(1.0 / sqrt(var + 1e-5));
    }
}

// ---------------- LN apply: Q,K -> tf32-rounded QK concat; V -> fp32 ----------------
__global__ void ln_apply_kernel(const float* __restrict__ kg, const float* __restrict__ kb,
                                const float* __restrict__ qg, const float* __restrict__ qb,
                                const float* __restrict__ vg, const float* __restrict__ vb) {
    int t = blockIdx.z;
    int bb = blockIdx.y;
    const float* base = (t==0 ? g_K : t==1 ? g_Q : g_V) + bb*PER_B;
    const float* g = t==0 ? kg : t==1 ? qg : vg;
    const float* be = t==0 ? kb : t==1 ? qb : vb;
    int off = (blockIdx.x*256 + threadIdx.x)*4;
    float mu = g_mu[t*NB+bb], rv = g_rv[t*NB+bb];
    float4 v  = *(const float4*)(base + off);
    float4 gg = *(const float4*)(g + off);
    float4 bv = *(const float4*)(be + off);
    float4 r;
    r.x = (v.x - mu)*rv*gg.x + bv.x;
    r.y = (v.y - mu)*rv*gg.y + bv.y;
    r.z = (v.z - mu)*rv*gg.z + bv.z;
    r.w = (v.w - mu)*rv*gg.w + bv.w;
    if (t == 2) {
        *(float4*)(g_V + bb*PER_B + off) = r;
    } else {
        int d = off & 63;
        int hp = off >> 6;
        size_t row = (size_t)bb*HEADS*NPIX + hp;
        int col = d + (t == 0 ? 64 : 0);
        float4 o;
        o.x = tf32r(r.x); o.y = tf32r(r.y); o.z = tf32r(r.z); o.w = tf32r(r.w);
        *(float4*)(g_QKf + row*128 + col) = o;
    }
}

// ---------------- V transpose (tf32-rounded): Vt[bh][d][p_pad] ----------------
__global__ void vtrans_kernel() {
    __shared__ float tile[32][65];
    int bhid = blockIdx.x;
    const float* Vb = g_V + (size_t)bhid*NPIX*DH;
    int t = threadIdx.x;
    for (int pt = 0; pt < 20; pt++) {
        int p0 = pt*32;
        for (int i = t; i < 32*64; i += 256) {
            int r = i >> 6, c = i & 63;
            tile[r][c] = (p0 + r < NPIX) ? Vb[(p0 + r)*DH + c] : 0.f;
        }
        __syncthreads();
        for (int i = t; i < 64*32; i += 256) {
            int d = i >> 5, pp = i & 31;
            g_Vt[((size_t)bhid*DH + d)*KPAD + p0 + pp] = tf32r(tile[pp][d]);
        }
        __syncthreads();
    }
}

// ---------------- prep: alin_w transposed, tf32-rounded ----------------
__global__ void prepw_kernel(const float* __restrict__ alw) {
    int idx = blockIdx.x*256 + threadIdx.x;
    if (idx >= KPAD*KPAD) return;
    int k = idx / KPAD, n = idx % KPAD;
    float v = (k < NPIX && n < NPIX) ? alw[k*NPIX + n] : 0.f;
    g_Wf[(size_t)n*KPAD + k] = tf32r(v);
}

// ---------------- prep: [qlw;klw] transposed, tf32-rounded ----------------
__global__ void prepwqk_kernel(const float* __restrict__ qlw, const float* __restrict__ klw) {
    int idx = blockIdx.x*256 + threadIdx.x;
    if (idx >= KPAD*128) return;
    int n = idx >> 7, k = idx & 127;
    float v = 0.f;
    if (n < NPIX) v = (k < 64) ? qlw[k*NPIX + n] : klw[(k-64)*NPIX + n];
    g_Wqkf[(size_t)n*128 + k] = tf32r(v);
}

// ---------------- prep: lin1_w transposed, tf32-rounded: W1t[64][256] ----------------
__global__ void prepw1_kernel(const float* __restrict__ w1) {
    int idx = blockIdx.x*256 + threadIdx.x;
    if (idx >= 64*256) return;
    int d = idx >> 8, c = idx & 255;
    g_W1t[d*256 + c] = tf32r(w1[c*64 + d]);
}

// ---------------- pipelined cp.async tile loaders (fp32, 128 thr) ----------------
__device__ __forceinline__ void cp_ftile_t128(float* dst, const float* g,
                                              size_t row0, int kc, int tid, int gstride) {
    #pragma unroll
    for (int j = 0; j < 8; j++) {
        int idx = tid + j*128;               // 0..1023
        int r = idx >> 3, q = idx & 7;
        cp16(dst + r*SKF + q*4, g + (row0 + r)*(size_t)gstride + kc + q*4);
    }
}

// ---------------- tf32 GEMM inner step: 4 warps, warp tile 64x64 ----------------
__device__ __forceinline__ void tf32_step4(const float* sA, const float* sW, int ko,
                                           int wm, int wn, int g, int tig,
                                           float acc[4][8][4]) {
    float af[4][4];
    #pragma unroll
    for (int mi = 0; mi < 4; mi++) {
        const float* ar = sA + (wm*64 + mi*16 + g)*SKF + ko + tig;
        af[mi][0] = ar[0];
        af[mi][1] = ar[8*SKF];
        af[mi][2] = ar[4];
        af[mi][3] = ar[8*SKF + 4];
    }
    #pragma unroll
    for (int nsub = 0; nsub < 8; nsub++) {
        const float* br = sW + (wn*64 + nsub*8 + g)*SKF + ko + tig;
        float b0 = br[0], b1 = br[4];
        #pragma unroll
        for (int mi = 0; mi < 4; mi++)
            mma_tf32(acc[mi][nsub], af[mi], b0, b1);
    }
}

// ---------------- logits GEMM (tf32, 128 thr): A = elu(QK @ Wqk^T + bias) ----------------
__global__ __launch_bounds__(128, 2) void logits_gemm_kernel(
    const float* __restrict__ qlb, const float* __restrict__ klb) {
    extern __shared__ float fsm[];
    int tid = threadIdx.x;
    int lane = tid & 31;
    int wid = tid >> 5;
    int wm = wid & 1, wn = wid >> 1;
    int g = lane >> 2, tig = lane & 3;
    int n0 = blockIdx.x * 128;
    size_t m0 = (size_t)blockIdx.y * 128;

    float acc[4][8][4];
    #pragma unroll
    for (int mi = 0; mi < 4; mi++)
        #pragma unroll
        for (int ni = 0; ni < 8; ni++)
            #pragma unroll
            for (int k = 0; k < 4; k++) acc[mi][ni][k] = 0.f;

    {
        float* b = fsm;
        cp_ftile_t128(b,        g_QKf,  m0, 0, tid, 128);
        cp_ftile_t128(b + FBUF, g_Wqkf, n0, 0, tid, 128);
        CP_COMMIT();
    }
    for (int ch = 0; ch < NCHL; ch++) {
        if (ch + 1 < NCHL) {
            float* b = fsm + ((ch+1)&1)*G_BUF;
            int kc = (ch+1)*KC;
            cp_ftile_t128(b,        g_QKf,  m0, kc, tid, 128);
            cp_ftile_t128(b + FBUF, g_Wqkf, n0, kc, tid, 128);
            CP_COMMIT();
            CP_WAIT1();
        } else {
            CP_WAIT0();
        }
        __syncthreads();
        const float* sA = fsm + (ch&1)*G_BUF;
        const float* sW = sA + FBUF;
        #pragma unroll
        for (int ks = 0; ks < 4; ks++)
            tf32_step4(sA, sW, ks*8, wm, wn, g, tig, acc);
        __syncthreads();
    }

    #pragma unroll
    for (int mi = 0; mi < 4; mi++) {
        #pragma unroll
        for (int nsub = 0; nsub < 8; nsub++) {
            int n = n0 + wn*64 + nsub*8 + tig*2;
            float b0 = (n < NPIX)   ? qlb[n] + klb[n]     : 0.f;
            float b1 = (n+1 < NPIX) ? qlb[n+1] + klb[n+1] : 0.f;
            #pragma unroll
            for (int half = 0; half < 2; half++) {
                size_t m = m0 + wm*64 + mi*16 + g + half*8;
                float2 o;
                o.x = tf32r(eluf(acc[mi][nsub][2*half]   + b0));
                o.y = tf32r(eluf(acc[mi][nsub][2*half+1] + b1));
                *(float2*)(g_A + m*KPAD + n) = o;
            }
        }
    }
}

// ---------------- main GEMM (tf32, 128 thr): S = A @ W^T + alb ----------------
__global__ __launch_bounds__(128, 2) void gemm_kernel(const float* __restrict__ alb) {
    extern __shared__ float fsm[];
    int tid = threadIdx.x;
    int lane = tid & 31;
    int wid = tid >> 5;
    int wm = wid & 1, wn = wid >> 1;
    int g = lane >> 2, tig = lane & 3;
    int n0 = blockIdx.x * 128;
    size_t m0 = (size_t)blockIdx.y * 128;

    float acc[4][8][4];
    #pragma unroll
    for (int mi = 0; mi < 4; mi++)
        #pragma unroll
        for (int ni = 0; ni < 8; ni++)
            #pragma unroll
            for (int k = 0; k < 4; k++) acc[mi][ni][k] = 0.f;

    {
        float* b = fsm;
        cp_ftile_t128(b,        g_A,  m0, 0, tid, KPAD);
        cp_ftile_t128(b + FBUF, g_Wf, n0, 0, tid, KPAD);
        CP_COMMIT();
    }
    for (int ch = 0; ch < NCH; ch++) {
        if (ch + 1 < NCH) {
            float* b = fsm + ((ch+1)&1)*G_BUF;
            int kc = (ch+1)*KC;
            cp_ftile_t128(b,        g_A,  m0, kc, tid, KPAD);
            cp_ftile_t128(b + FBUF, g_Wf, n0, kc, tid, KPAD);
            CP_COMMIT();
            CP_WAIT1();
        } else {
            CP_WAIT0();
        }
        __syncthreads();
        const float* sA = fsm + (ch&1)*G_BUF;
        const float* sW = sA + FBUF;
        #pragma unroll
        for (int ks = 0; ks < 4; ks++)
            tf32_step4(sA, sW, ks*8, wm, wn, g, tig, acc);
        __syncthreads();
    }

    #pragma unroll
    for (int mi = 0; mi < 4; mi++) {
        #pragma unroll
        for (int nsub = 0; nsub < 8; nsub++) {
            int n = n0 + wn*64 + nsub*8 + tig*2;
            #pragma unroll
            for (int half = 0; half < 2; half++) {
                size_t m = m0 + wm*64 + mi*16 + g + half*8;
                if (n + 1 < NPIX) {
                    float2 o;
                    o.x = acc[mi][nsub][2*half]   + alb[n];
                    o.y = acc[mi][nsub][2*half+1] + alb[n+1];
                    *(float2*)(g_S + m*NPIX + n) = o;
                } else if (n < NPIX) {
                    g_S[m*NPIX + n] = acc[mi][nsub][2*half] + alb[n];
                }
            }
        }
    }
}

// ---------------- softmax: g_S -> g_P (tf32-rounded, zero-padded) ----------------
__global__ __launch_bounds__(256) void softmax_kernel() {
    size_t row = (size_t)blockIdx.x*8 + (threadIdx.x >> 5);
    int lane = threadIdx.x & 31;
    const float* S = g_S + row*NPIX;
    float* P = g_P + row*KPAD;
    float v[19];
    float m = -1e30f;
    #pragma unroll
    for (int i = 0; i < 19; i++) {
        int j = lane + 32*i;
        v[i] = (j < NPIX) ? S[j] : -1e30f;
        m = fmaxf(m, v[i]);
    }
    #pragma unroll
    for (int o = 16; o; o >>= 1) m = fmaxf(m, __shfl_xor_sync(0xffffffffu, m, o));
    float s = 0.f;
    #pragma unroll
    for (int i = 0; i < 19; i++) {
        v[i] = __expf(v[i] - m);
        s += v[i];
    }
    #pragma unroll
    for (int o = 16; o; o >>= 1) s += __shfl_xor_sync(0xffffffffu, s, o);
    float inv = 1.f / s;
    #pragma unroll
    for (int i = 0; i < 19; i++) {
        int j = lane + 32*i;
        if (j < NPIX) P[j] = tf32r(v[i]*inv);
        else          P[j] = 0.f;
    }
    P[608 + lane] = 0.f;
}

// ---------------- E GEMM (tf32): E = P @ Vt^T per bh (tf32-rounded out) ----------------
__global__ __launch_bounds__(256, 2) void e_gemm_kernel() {
    extern __shared__ float fsm[];
    int tid = threadIdx.x;
    int lane = tid & 31;
    int wid = tid >> 5;
    int g = lane >> 2, tig = lane & 3;
    int mt = blockIdx.x;
    int bhid = blockIdx.y;
    int p00 = mt * 128;
    int bb = bhid >> 2, h = bhid & 3;

    float acc[8][4];
    #pragma unroll
    for (int ni = 0; ni < 8; ni++)
        #pragma unroll
        for (int k = 0; k < 4; k++) acc[ni][k] = 0.f;

    auto loadT = [&](float* b, int kc) {
        #pragma unroll
        for (int j = 0; j < 4; j++) {
            int idx = tid + j*256;
            int r = idx >> 3, q = idx & 7;
            int p = p00 + r; if (p > NPIX-1) p = NPIX-1;
            cp16(b + r*SKF + q*4, g_P + ((size_t)bhid*NPIX + p)*KPAD + kc + q*4);
        }
        #pragma unroll
        for (int j = 0; j < 2; j++) {
            int idx = tid + j*256;
            int r = idx >> 3, q = idx & 7;
            cp16(b + FBUF + r*SKF + q*4, g_Vt + ((size_t)bhid*DH + r)*KPAD + kc + q*4);
        }
    };

    loadT(fsm, 0);
    CP_COMMIT();
    for (int ch = 0; ch < NCH; ch++) {
        if (ch + 1 < NCH) {
            loadT(fsm + ((ch+1)&1)*E_BUF, (ch+1)*KC);
            CP_COMMIT();
            CP_WAIT1();
        } else {
            CP_WAIT0();
        }
        __syncthreads();
        const float* sP = fsm + (ch&1)*E_BUF;
        const float* sV = sP + FBUF;
        #pragma unroll
        for (int ks = 0; ks < 4; ks++) {
            int ko = ks*8;
            float af[4];
            const float* ar = sP + (wid*16 + g)*SKF + ko + tig;
            af[0] = ar[0];
            af[1] = ar[8*SKF];
            af[2] = ar[4];
            af[3] = ar[8*SKF + 4];
            #pragma unroll
            for (int nsub = 0; nsub < 8; nsub++) {
                const float* br = sV + (nsub*8 + g)*SKF + ko + tig;
                mma_tf32(acc[nsub], af, br[0], br[4]);
            }
        }
        __syncthreads();
    }

    #pragma unroll
    for (int nsub = 0; nsub < 8; nsub++) {
        int d = nsub*8 + tig*2;
        #pragma unroll
        for (int half = 0; half < 2; half++) {
            int p = p00 + wid*16 + g + half*8;
            if (p < NPIX) {
                float2 o;
                o.x = tf32r(acc[nsub][2*half]);
                o.y = tf32r(acc[nsub][2*half+1]);
                *(float2*)(g_E + ((size_t)bb*NPIX + p)*256 + h*DH + d) = o;
            }
        }
    }
}

// ---------------- lin1 GEMM (tf32): F = relu(E @ W1t^T + b) ----------------
__global__ __launch_bounds__(256, 2) void lin1_gemm_kernel(const float* __restrict__ b1) {
    extern __shared__ float fsm[];
    int tid = threadIdx.x;
    int lane = tid & 31;
    int wid = tid >> 5;
    int g = lane >> 2, tig = lane & 3;
    size_t m0 = (size_t)blockIdx.x * 128;

    float acc[8][4];
    #pragma unroll
    for (int ni = 0; ni < 8; ni++)
        #pragma unroll
        for (int k = 0; k < 4; k++) acc[ni][k] = 0.f;

    auto loadT = [&](float* b, int kc) {
        #pragma unroll
        for (int j = 0; j < 4; j++) {
            int idx = tid + j*256;
            int r = idx >> 3, q = idx & 7;
            cp16(b + r*SKF + q*4, g_E + (m0 + r)*256 + kc + q*4);
        }
        #pragma unroll
        for (int j = 0; j < 2; j++) {
            int idx = tid + j*256;
            int r = idx >> 3, q = idx & 7;
            cp16(b + FBUF + r*SKF + q*4, g_W1t + r*256 + kc + q*4);
        }
    };

    loadT(fsm, 0);
    CP_COMMIT();
    for (int ch = 0; ch < NCH1; ch++) {
        if (ch + 1 < NCH1) {
            loadT(fsm + ((ch+1)&1)*E_BUF, (ch+1)*KC);
            CP_COMMIT();
            CP_WAIT1();
        } else {
            CP_WAIT0();
        }
        __syncthreads();
        const float* sE = fsm + (ch&1)*E_BUF;
        const float* sW = sE + FBUF;
        #pragma unroll
        for (int ks = 0; ks < 4; ks++) {
            int ko = ks*8;
            float af[4];
            const float* ar = sE + (wid*16 + g)*SKF + ko + tig;
            af[0] = ar[0];
            af[1] = ar[8*SKF];
            af[2] = ar[4];
            af[3] = ar[8*SKF + 4];
            #pragma unroll
            for (int nsub = 0; nsub < 8; nsub++) {
                const float* br = sW + (nsub*8 + g)*SKF + ko + tig;
                mma_tf32(acc[nsub], af, br[0], br[4]);
            }
        }
        __syncthreads();
    }

    #pragma unroll
    for (int nsub = 0; nsub < 8; nsub++) {
        int d = nsub*8 + tig*2;
        float bb0 = b1[d], bb1 = b1[d+1];
        #pragma unroll
        for (int half = 0; half < 2; half++) {
            size_t m = m0 + wid*16 + g + half*8;
            float2 o;
            o.x = fmaxf(acc[nsub][2*half]   + bb0, 0.f);
            o.y = fmaxf(acc[nsub][2*half+1] + bb1, 0.f);
            *(float2*)(g_F + m*DH + d) = o;
        }
    }
}

// ---------------- LN2 stats ----------------
__global__ void ln2_stats_kernel() {
    int bb = blockIdx.x;
    const float4* base = (const float4*)(g_F + bb*NPIX*DH);
    const int n4 = NPIX*DH/4;
    float s = 0.f, ss = 0.f;
    for (int i = threadIdx.x; i < n4; i += blockDim.x) {
        float4 v = base[i];
        s  += v.x + v.y + v.z + v.w;
        ss += v.x*v.x + v.y*v.y + v.z*v.z + v.w*v.w;
    }
    __shared__ double sh[256], sh2[256];
    sh[threadIdx.x] = (double)s; sh2[threadIdx.x] = (double)ss; __syncthreads();
    for (int o = 128; o; o >>= 1) {
        if (threadIdx.x < o) { sh[threadIdx.x] += sh[threadIdx.x+o]; sh2[threadIdx.x] += sh2[threadIdx.x+o]; }
        __syncthreads();
    }
    if (threadIdx.x == 0) {
        const int n = NPIX*DH;
        double m = sh[0] / (double)n;
        double var = sh2[0] / (double)n - m*m;
        g_mu2[bb] = (float)m;
        g_rv2[bb] = (float)(1.0 / sqrt(var + 1e-5));
    }
}

// ---------------- LN2 apply + max ----------------
__global__ void ln2max_kernel() {
    int bb = blockIdx.x;
    int d = threadIdx.x & 63, pc = threadIdx.x >> 6;
    float mu = g_mu2[bb], rv = g_rv2[bb];
    float m = -1e30f;
    for (int p = pc; p < NPIX; p += 4) {
        float v = (g_F[(bb*NPIX + p)*DH + d] - mu) * rv;
        m = fmaxf(m, v);
    }
    __shared__ float sh[256];
    sh[threadIdx.x] = m; __syncthreads();
    if (pc == 0) {
        m = fmaxf(fmaxf(sh[d], sh[64+d]), fmaxf(sh[128+d], sh[192+d]));
        g_M[bb*DH + d] = m;
    }
}

// ---------------- final lin2 + elu ----------------
__global__ void final_kernel(const float* __restrict__ w, const float* __restrict__ b,
                             float* __restrict__ out) {
    int idx = blockIdx.x * blockDim.x + threadIdx.x;
    if (idx >= NB*10) return;
    int bb = idx / 10, j = idx % 10;
    float acc = b[j];
    #pragma unroll
    for (int d = 0; d < DH; d++) acc += g_M[bb*DH + d] * w[d*10 + j];
    out[idx] = eluf(acc);
}

extern "C" void kernel_launch(void* const* d_in, const int* in_sizes, int n_in,
                              void* d_out, int out_size) {
    const float* x       = (const float*)d_in[0];
    const float* conv1_w = (const float*)d_in[1];
    const float* conv1_b = (const float*)d_in[2];
    const float* conv2_w = (const float*)d_in[3];
    const float* conv2_b = (const float*)d_in[4];
    const float* kp_w    = (const float*)d_in[5];
    const float* kp_b    = (const float*)d_in[6];
    const float* qp_w    = (const float*)d_in[7];
    const float* qp_b    = (const float*)d_in[8];
    const float* vp_w    = (const float*)d_in[9];
    const float* vp_b    = (const float*)d_in[10];
    const float* klin_w  = (const float*)d_in[11];
    const float* klin_b  = (const float*)d_in[12];
    const float* qlin_w  = (const float*)d_in[13];
    const float* qlin_b  = (const float*)d_in[14];
    const float* alin_w  = (const float*)d_in[15];
    const float* alin_b  = (const float*)d_in[16];
    const float* knorm_g = (const float*)d_in[17];
    const float* knorm_b = (const float*)d_in[18];
    const float* qnorm_g = (const float*)d_in[19];
    const float* qnorm_b = (const float*)d_in[20];
    const float* vnorm_g = (const float*)d_in[21];
    const float* vnorm_b = (const float*)d_in[22];
    const float* lin1_w  = (const float*)d_in[23];
    const float* lin1_b  = (const float*)d_in[24];
    const float* lin2_w  = (const float*)d_in[25];
    const float* lin2_b  = (const float*)d_in[26];
    float* out = (float*)d_out;

    cudaFuncSetAttribute(logits_gemm_kernel, cudaFuncAttributeMaxDynamicSharedMemorySize, GEMM_SMEM);
    cudaFuncSetAttribute(gemm_kernel,        cudaFuncAttributeMaxDynamicSharedMemorySize, GEMM_SMEM);
    cudaFuncSetAttribute(e_gemm_kernel,      cudaFuncAttributeMaxDynamicSharedMemorySize, EGEMM_SMEM);
    cudaFuncSetAttribute(lin1_gemm_kernel,   cudaFuncAttributeMaxDynamicSharedMemorySize, EGEMM_SMEM);

    conv1_kernel<<<(NB*16*150*5 + 255)/256, 256>>>(x, conv1_w, conv1_b);
    conv2_feats_kernel<<<(NB*NPIX*34 + 255)/256, 256>>>(conv2_w, conv2_b);
    {
        dim3 g((NB*NPIX*256 + 255)/256, 3);
        proj_kernel<<<g, 256>>>(kp_w, kp_b, qp_w, qp_b, vp_w, vp_b);
    }
    {
        dim3 g(NB, 3);
        ln_stats_kernel<<<g, 512>>>();
    }
    {
        dim3 g(PER_B/1024, NB, 3);
        ln_apply_kernel<<<g, 256>>>(knorm_g, knorm_b, qnorm_g, qnorm_b, vnorm_g, vnorm_b);
    }
    prepwqk_kernel<<<(KPAD*128 + 255)/256, 256>>>(qlin_w, klin_w);
    {
        dim3 g(KPAD/128, MROWS/128);               // (5, 1192)
        logits_gemm_kernel<<<g, 128, GEMM_SMEM>>>(qlin_b, klin_b);
    }
    prepw_kernel<<<(KPAD*KPAD + 255)/256, 256>>>(alin_w);
    {
        dim3 g(KPAD/128, MROWS/128);               // (5, 1192)
        gemm_kernel<<<g, 128, GEMM_SMEM>>>(alin_b);
    }
    vtrans_kernel<<<NB*HEADS, 256>>>();
    softmax_kernel<<<MROWS/8, 256>>>();
    {
        dim3 g(5, NB*HEADS);                       // (5, 256)
        e_gemm_kernel<<<g, 256, EGEMM_SMEM>>>();
    }
    prepw1_kernel<<<(64*256 + 255)/256, 256>>>(lin1_w);
    lin1_gemm_kernel<<<EROWS/128, 256, EGEMM_SMEM>>>(lin1_b);
    ln2_stats_kernel<<<NB, 256>>>();
    ln2max_kernel<<<NB, 256>>>();
    final_kernel<<<3, 256>>>(lin2_w, lin2_b, out);
}